// round 7
// baseline (speedup 1.0000x reference)
#include <cuda_runtime.h>
#include <cuda_fp16.h>
#include <math.h>

// ---------------- problem constants ----------------
#define B_   64
#define C_   384
#define HW_  256            // n = H*W
#define MTOT (B_*HW_)       // 16384
#define HEADS 8
#define DHEAD 32
#define INNER (HEADS*DHEAD) // 256
#define HID   (4*C_)        // 1536

// ---------------- device scratch (allocation-free rule) ----------------
__device__ float g_t  [MTOT*C_];
__device__ float g_a  [MTOT*C_];
__device__ float g_f  [MTOT*C_];
__device__ float g_qkv[MTOT*3*INNER];
__device__ float g_o  [MTOT*INNER];
__device__ float g_s1 [MTOT*C_];
__device__ float g_ff [MTOT*C_];
__device__ float g_g  [MTOT*HID];

// ---------------- tiled transpose + dual LayerNorm (coalesced) ----------------
// grid (HW_/32, B_), 256 threads. Phase 1: load x[b][c][p0..p0+31] coalesced
// (float4 along p) into smem tile[c][p] (pitch 33). Phase 2: 8 threads per p-row
// reduce over 384 channels via width-8 shuffles; coalesced float4 writes.
#define LN_SMEM (C_*33*4)
__global__ __launch_bounds__(256)
void ln_tile_kernel(const float* __restrict__ x,
                    const float* __restrict__ g1, const float* __restrict__ b1,
                    const float* __restrict__ g2, const float* __restrict__ b2,
                    float* __restrict__ t, float* __restrict__ a, float* __restrict__ f)
{
    extern __shared__ float tile[];   // [C_][33]
    const int tid = threadIdx.x;
    const int p0  = blockIdx.x * 32;
    const int b   = blockIdx.y;

    // phase 1: 3072 float4 loads, coalesced along p
    #pragma unroll
    for (int i = 0; i < 12; i++) {
        int l  = tid + i*256;          // 0..3071
        int c  = l >> 3;
        int p4 = (l & 7) * 4;
        float4 v = *(const float4*)&x[((size_t)b*C_ + c)*HW_ + p0 + p4];
        tile[c*33 + p4 + 0] = v.x;
        tile[c*33 + p4 + 1] = v.y;
        tile[c*33 + p4 + 2] = v.z;
        tile[c*33 + p4 + 3] = v.w;
    }
    __syncthreads();

    // phase 2: group of 8 threads per p; thread jj handles c4 = (jj+8i)*4
    const int jj = tid & 7;
    const int pp = tid >> 3;           // 0..31

    float vals[48];
    #pragma unroll
    for (int i = 0; i < 12; i++) {
        int c4 = (jj + 8*i) * 4;
        #pragma unroll
        for (int k = 0; k < 4; k++)
            vals[i*4 + k] = tile[(c4 + k)*33 + pp];
    }

    float s = 0.f;
    #pragma unroll
    for (int v = 0; v < 48; v++) s += vals[v];
    #pragma unroll
    for (int o = 4; o; o >>= 1) s += __shfl_down_sync(0xffffffffu, s, o, 8);
    float mean = __shfl_sync(0xffffffffu, s, 0, 8) * (1.f/384.f);

    float sq = 0.f;
    #pragma unroll
    for (int v = 0; v < 48; v++) { float d = vals[v] - mean; sq += d*d; }
    #pragma unroll
    for (int o = 4; o; o >>= 1) sq += __shfl_down_sync(0xffffffffu, sq, o, 8);
    float rstd = rsqrtf(__shfl_sync(0xffffffffu, sq, 0, 8) * (1.f/384.f) + 1e-5f);

    const size_t base = (size_t)(b*HW_ + p0 + pp) * C_;
    #pragma unroll
    for (int i = 0; i < 12; i++) {
        int c4 = (jj + 8*i) * 4;
        float4 tv = make_float4(vals[i*4+0], vals[i*4+1], vals[i*4+2], vals[i*4+3]);
        *(float4*)&t[base + c4] = tv;
        float4 G1 = *(const float4*)&g1[c4];
        float4 B1 = *(const float4*)&b1[c4];
        float4 G2 = *(const float4*)&g2[c4];
        float4 B2 = *(const float4*)&b2[c4];
        float n0 = (tv.x - mean)*rstd, n1 = (tv.y - mean)*rstd;
        float n2 = (tv.z - mean)*rstd, n3 = (tv.w - mean)*rstd;
        *(float4*)&a[base + c4] = make_float4(n0*G1.x+B1.x, n1*G1.y+B1.y, n2*G1.z+B1.z, n3*G1.w+B1.w);
        *(float4*)&f[base + c4] = make_float4(n0*G2.x+B2.x, n1*G2.y+B2.y, n2*G2.z+B2.z, n3*G2.w+B2.w);
    }
}

// ---------------- tf32 tensor-core GEMM, 3-stage cp.async pipeline ----------------
// dynamic smem: As stages (128x20 fl) then Bs stages (16x136 fl)
#define AS_STRIDE 2560            // 128*20
#define BS_STRIDE 2176            // 16*136
#define TG_SMEM  ((3*AS_STRIDE + 3*BS_STRIDE)*4)   // 56832 B

__global__ __launch_bounds__(256, 2)
void tgemm_kernel(const float* __restrict__ A, const float* __restrict__ Bm,
                  float* __restrict__ C, int M, int N, int K,
                  const float* __restrict__ bias, const float* __restrict__ add,
                  int do_gelu)
{
    extern __shared__ float dsm[];
    float* Asm = dsm;                     // 3 stages of [128][20]
    float* Bsm = dsm + 3*AS_STRIDE;       // 3 stages of [16][136]

    const int tid  = threadIdx.x;
    const int warp = tid >> 5;
    const int lane = tid & 31;
    const int g    = lane >> 2;
    const int t4   = lane & 3;

    const int brow = blockIdx.y * 128;
    const int bcol = blockIdx.x * 128;

    const int wr = warp & 3;
    const int wc = warp >> 2;

    float acc[2][8][4];
    #pragma unroll
    for (int mi = 0; mi < 2; mi++)
        #pragma unroll
        for (int ni = 0; ni < 8; ni++)
            #pragma unroll
            for (int e = 0; e < 4; e++) acc[mi][ni][e] = 0.f;

    const int a_row = tid >> 2;
    const int a_c4  = (tid & 3) * 4;
    const int b_kr  = tid >> 5;
    const int b_c4  = (tid & 31) * 4;

    auto issue = [&](int kt, int buf) {
        int k0 = kt * 16;
        float* as = Asm + buf*AS_STRIDE;
        float* bs = Bsm + buf*BS_STRIDE;
        #pragma unroll
        for (int q = 0; q < 2; q++) {
            const float* src = &A[(size_t)(brow + a_row + q*64)*K + k0 + a_c4];
            unsigned dst = (unsigned)__cvta_generic_to_shared(&as[(a_row + q*64)*20 + a_c4]);
            asm volatile("cp.async.cg.shared.global [%0], [%1], 16;" :: "r"(dst), "l"(src));
        }
        #pragma unroll
        for (int q = 0; q < 2; q++) {
            const float* src = &Bm[(size_t)(k0 + b_kr + q*8)*N + bcol + b_c4];
            unsigned dst = (unsigned)__cvta_generic_to_shared(&bs[(b_kr + q*8)*136 + b_c4]);
            asm volatile("cp.async.cg.shared.global [%0], [%1], 16;" :: "r"(dst), "l"(src));
        }
        asm volatile("cp.async.commit_group;");
    };

    auto compute = [&](int buf) {
        const float* as = Asm + buf*AS_STRIDE;
        const float* bs = Bsm + buf*BS_STRIDE;
        #pragma unroll
        for (int ch = 0; ch < 2; ch++) {
            unsigned a[2][4];
            #pragma unroll
            for (int mi = 0; mi < 2; mi++) {
                int r0 = wr*32 + mi*16 + g;
                a[mi][0] = __float_as_uint(as[r0*20       + ch*8 + t4    ]);
                a[mi][1] = __float_as_uint(as[(r0+8)*20   + ch*8 + t4    ]);
                a[mi][2] = __float_as_uint(as[r0*20       + ch*8 + t4 + 4]);
                a[mi][3] = __float_as_uint(as[(r0+8)*20   + ch*8 + t4 + 4]);
            }
            #pragma unroll
            for (int ni = 0; ni < 8; ni++) {
                int col = wc*64 + ni*8 + g;
                unsigned b0 = __float_as_uint(bs[(ch*8 + t4)*136     + col]);
                unsigned b1 = __float_as_uint(bs[(ch*8 + t4 + 4)*136 + col]);
                #pragma unroll
                for (int mi = 0; mi < 2; mi++) {
                    asm volatile(
                        "mma.sync.aligned.m16n8k8.row.col.f32.tf32.tf32.f32 "
                        "{%0,%1,%2,%3},{%4,%5,%6,%7},{%8,%9},{%0,%1,%2,%3};"
                        : "+f"(acc[mi][ni][0]), "+f"(acc[mi][ni][1]),
                          "+f"(acc[mi][ni][2]), "+f"(acc[mi][ni][3])
                        : "r"(a[mi][0]), "r"(a[mi][1]), "r"(a[mi][2]), "r"(a[mi][3]),
                          "r"(b0), "r"(b1));
                }
            }
        }
    };

    const int nkt = K >> 4;          // >= 16 for all our shapes
    int buf0 = 0, buf1 = 1, buf2 = 2;
    issue(0, 0);
    issue(1, 1);
    for (int kt = 0; kt < nkt; kt++) {
        if (kt + 1 < nkt) { asm volatile("cp.async.wait_group 1;"); }
        else              { asm volatile("cp.async.wait_group 0;"); }
        __syncthreads();
        if (kt + 2 < nkt) issue(kt + 2, buf2);
        compute(buf0);
        int tmp = buf0; buf0 = buf1; buf1 = buf2; buf2 = tmp;
    }

    // ---- epilogue ----
    #pragma unroll
    for (int mi = 0; mi < 2; mi++) {
        int r0 = brow + wr*32 + mi*16 + g;
        #pragma unroll
        for (int ni = 0; ni < 8; ni++) {
            int col = bcol + wc*64 + ni*8 + 2*t4;
            float v0 = acc[mi][ni][0];
            float v1 = acc[mi][ni][1];
            float v2 = acc[mi][ni][2];
            float v3 = acc[mi][ni][3];
            if (bias) {
                float bz0 = bias[col], bz1 = bias[col+1];
                v0 += bz0; v1 += bz1; v2 += bz0; v3 += bz1;
            }
            if (do_gelu) {
                v0 = 0.5f*v0*(1.f + erff(v0*0.70710678118654752f));
                v1 = 0.5f*v1*(1.f + erff(v1*0.70710678118654752f));
                v2 = 0.5f*v2*(1.f + erff(v2*0.70710678118654752f));
                v3 = 0.5f*v3*(1.f + erff(v3*0.70710678118654752f));
            }
            if (add) {
                float2 a0 = *(const float2*)&add[(size_t)r0*N + col];
                float2 a1 = *(const float2*)&add[(size_t)(r0+8)*N + col];
                v0 += a0.x; v1 += a0.y; v2 += a1.x; v3 += a1.y;
            }
            *(float2*)&C[(size_t)r0*N + col]     = make_float2(v0, v1);
            *(float2*)&C[(size_t)(r0+8)*N + col] = make_float2(v2, v3);
        }
    }
}

// ---------------- tensor-core attention (unchanged from R5) ----------------
#define ATT_KS_F   (256*36)
#define ATT_VS_H   (32*264)
#define ATT_SMEM_B (ATT_KS_F*4 + ATT_VS_H*2 + 961*4)

__global__ void attn_mma_kernel(const float* __restrict__ qkv,
                                const float* __restrict__ bias_table,
                                float* __restrict__ o)
{
    extern __shared__ float sm[];
    float*  ks  = sm;
    __half* vs  = (__half*)(sm + ATT_KS_F);
    float*  bsh = sm + ATT_KS_F + ATT_VS_H/2;

    const int b = blockIdx.x >> 3, h = blockIdx.x & 7;
    const int tid = threadIdx.x, warp = tid >> 5, lane = tid & 31;
    const int g = lane >> 2, t4 = lane & 3;
    const float* base = qkv + (size_t)b * HW_ * 768;

    for (int l = tid; l < 2048; l += 256) {
        int j = l >> 3, c4 = (l & 7) * 4;
        float4 kv = *(const float4*)&base[(size_t)j*768 + 256 + h*32 + c4];
        *(float4*)&ks[j*36 + c4] = kv;
        float4 vv = *(const float4*)&base[(size_t)j*768 + 512 + h*32 + c4];
        vs[(c4+0)*264 + j] = __float2half(vv.x);
        vs[(c4+1)*264 + j] = __float2half(vv.y);
        vs[(c4+2)*264 + j] = __float2half(vv.z);
        vs[(c4+3)*264 + j] = __float2half(vv.w);
    }
    for (int l = tid; l < 961; l += 256) bsh[l] = bias_table[(size_t)l*8 + h];

    const float scale = 0.17677669529663688f;
    unsigned qa[2][4][4];
    #pragma unroll
    for (int mi = 0; mi < 2; mi++) {
        int r0 = warp*32 + mi*16 + g;
        const float* q0 = &base[(size_t)r0*768 + h*32];
        const float* q1 = &base[(size_t)(r0+8)*768 + h*32];
        #pragma unroll
        for (int k = 0; k < 4; k++) {
            qa[mi][k][0] = __float_as_uint(q0[k*8 + t4]     * scale);
            qa[mi][k][1] = __float_as_uint(q1[k*8 + t4]     * scale);
            qa[mi][k][2] = __float_as_uint(q0[k*8 + t4 + 4] * scale);
            qa[mi][k][3] = __float_as_uint(q1[k*8 + t4 + 4] * scale);
        }
    }

    int bb[2][2];
    #pragma unroll
    for (int mi = 0; mi < 2; mi++) {
        int i0 = warp*32 + mi*16 + g;
        bb[mi][0] = ((i0 >> 4) + 15)*31 + (i0 & 15) + 15;
        bb[mi][1] = (((i0+8) >> 4) + 15)*31 + ((i0+8) & 15) + 15;
    }
    __syncthreads();

    float acco[2][4][4];
    #pragma unroll
    for (int mi = 0; mi < 2; mi++)
        #pragma unroll
        for (int vn = 0; vn < 4; vn++)
            #pragma unroll
            for (int e = 0; e < 4; e++) acco[mi][vn][e] = 0.f;
    float rs[2][2] = {{0.f, 0.f}, {0.f, 0.f}};

    for (int j0 = 0; j0 < 256; j0 += 32) {
        float accs[2][4][4];
        #pragma unroll
        for (int mi = 0; mi < 2; mi++)
            #pragma unroll
            for (int ni = 0; ni < 4; ni++)
                #pragma unroll
                for (int e = 0; e < 4; e++) accs[mi][ni][e] = 0.f;

        #pragma unroll
        for (int k = 0; k < 4; k++) {
            #pragma unroll
            for (int ni = 0; ni < 4; ni++) {
                unsigned kb0 = __float_as_uint(ks[(j0 + ni*8 + g)*36 + k*8 + t4]);
                unsigned kb1 = __float_as_uint(ks[(j0 + ni*8 + g)*36 + k*8 + t4 + 4]);
                #pragma unroll
                for (int mi = 0; mi < 2; mi++) {
                    asm volatile(
                        "mma.sync.aligned.m16n8k8.row.col.f32.tf32.tf32.f32 "
                        "{%0,%1,%2,%3},{%4,%5,%6,%7},{%8,%9},{%0,%1,%2,%3};"
                        : "+f"(accs[mi][ni][0]), "+f"(accs[mi][ni][1]),
                          "+f"(accs[mi][ni][2]), "+f"(accs[mi][ni][3])
                        : "r"(qa[mi][k][0]), "r"(qa[mi][k][1]),
                          "r"(qa[mi][k][2]), "r"(qa[mi][k][3]),
                          "r"(kb0), "r"(kb1));
                }
            }
        }

        unsigned pk[2][4][2];
        #pragma unroll
        for (int mi = 0; mi < 2; mi++) {
            #pragma unroll
            for (int ni = 0; ni < 4; ni++) {
                int j  = j0 + ni*8 + 2*t4;
                int o0 = (j >> 4)*31 + (j & 15);
                int o1 = ((j+1) >> 4)*31 + ((j+1) & 15);
                float p0 = __expf(accs[mi][ni][0] + bsh[bb[mi][0] - o0]);
                float p1 = __expf(accs[mi][ni][1] + bsh[bb[mi][0] - o1]);
                float p2 = __expf(accs[mi][ni][2] + bsh[bb[mi][1] - o0]);
                float p3 = __expf(accs[mi][ni][3] + bsh[bb[mi][1] - o1]);
                rs[mi][0] += p0 + p1;
                rs[mi][1] += p2 + p3;
                __half2 h01 = __floats2half2_rn(p0, p1);
                __half2 h23 = __floats2half2_rn(p2, p3);
                pk[mi][ni][0] = *(unsigned*)&h01;
                pk[mi][ni][1] = *(unsigned*)&h23;
            }
        }

        #pragma unroll
        for (int k = 0; k < 2; k++) {
            #pragma unroll
            for (int vn = 0; vn < 4; vn++) {
                unsigned vb0 = *(const unsigned*)&vs[(vn*8 + g)*264 + j0 + k*16 + 2*t4];
                unsigned vb1 = *(const unsigned*)&vs[(vn*8 + g)*264 + j0 + k*16 + 2*t4 + 8];
                #pragma unroll
                for (int mi = 0; mi < 2; mi++) {
                    asm volatile(
                        "mma.sync.aligned.m16n8k16.row.col.f32.f16.f16.f32 "
                        "{%0,%1,%2,%3},{%4,%5,%6,%7},{%8,%9},{%0,%1,%2,%3};"
                        : "+f"(acco[mi][vn][0]), "+f"(acco[mi][vn][1]),
                          "+f"(acco[mi][vn][2]), "+f"(acco[mi][vn][3])
                        : "r"(pk[mi][2*k][0]), "r"(pk[mi][2*k][1]),
                          "r"(pk[mi][2*k+1][0]), "r"(pk[mi][2*k+1][1]),
                          "r"(vb0), "r"(vb1));
                }
            }
        }
    }

    #pragma unroll
    for (int mi = 0; mi < 2; mi++)
        #pragma unroll
        for (int r = 0; r < 2; r++) {
            float v = rs[mi][r];
            v += __shfl_xor_sync(0xffffffffu, v, 1);
            v += __shfl_xor_sync(0xffffffffu, v, 2);
            rs[mi][r] = 1.f / v;
        }

    #pragma unroll
    for (int mi = 0; mi < 2; mi++) {
        int r0 = warp*32 + mi*16 + g;
        #pragma unroll
        for (int vn = 0; vn < 4; vn++) {
            int col = h*32 + vn*8 + 2*t4;
            *(float2*)&o[((size_t)(b*HW_) + r0)*INNER + col] =
                make_float2(acco[mi][vn][0]*rs[mi][0], acco[mi][vn][1]*rs[mi][0]);
            *(float2*)&o[((size_t)(b*HW_) + r0 + 8)*INNER + col] =
                make_float2(acco[mi][vn][2]*rs[mi][1], acco[mi][vn][3]*rs[mi][1]);
        }
    }
}

// ---------------- fused join: out[B,C,H,W] = transpose(s1 + ff) ----------------
__global__ void transpose_add_kernel(const float* __restrict__ s1,
                                     const float* __restrict__ ff,
                                     float* __restrict__ out)
{
    __shared__ float tile[32][33];
    int b  = blockIdx.z;
    int c0 = blockIdx.x * 32;
    int p0 = blockIdx.y * 32;

    for (int i = threadIdx.y; i < 32; i += 8) {
        size_t idx = (size_t)(b*HW_ + p0 + i)*C_ + c0 + threadIdx.x;
        tile[i][threadIdx.x] = s1[idx] + ff[idx];
    }
    __syncthreads();
    float* ob = out + (size_t)b * C_ * HW_;
    for (int i = threadIdx.y; i < 32; i += 8)
        ob[(size_t)(c0 + i)*HW_ + p0 + threadIdx.x] = tile[threadIdx.x][i];
}

// ---------------- launch ----------------
extern "C" void kernel_launch(void* const* d_in, const int* in_sizes, int n_in,
                              void* d_out, int out_size)
{
    const float* x          = (const float*)d_in[0];
    const float* ln1_g      = (const float*)d_in[1];
    const float* ln1_b      = (const float*)d_in[2];
    const float* w_qkv      = (const float*)d_in[3];
    const float* bias_table = (const float*)d_in[4];
    const float* w_out      = (const float*)d_in[5];
    const float* b_out      = (const float*)d_in[6];
    const float* ln2_g      = (const float*)d_in[7];
    const float* ln2_b      = (const float*)d_in[8];
    const float* w_ff1      = (const float*)d_in[9];
    const float* b_ff1      = (const float*)d_in[10];
    const float* w_ff2      = (const float*)d_in[11];
    const float* b_ff2      = (const float*)d_in[12];

    float *t, *a, *f, *qkv, *o, *s1, *ff, *g;
    cudaGetSymbolAddress((void**)&t,   g_t);
    cudaGetSymbolAddress((void**)&a,   g_a);
    cudaGetSymbolAddress((void**)&f,   g_f);
    cudaGetSymbolAddress((void**)&qkv, g_qkv);
    cudaGetSymbolAddress((void**)&o,   g_o);
    cudaGetSymbolAddress((void**)&s1,  g_s1);
    cudaGetSymbolAddress((void**)&ff,  g_ff);
    cudaGetSymbolAddress((void**)&g,   g_g);

    cudaFuncSetAttribute(attn_mma_kernel, cudaFuncAttributeMaxDynamicSharedMemorySize, ATT_SMEM_B);
    cudaFuncSetAttribute(tgemm_kernel,    cudaFuncAttributeMaxDynamicSharedMemorySize, TG_SMEM);
    cudaFuncSetAttribute(ln_tile_kernel,  cudaFuncAttributeMaxDynamicSharedMemorySize, LN_SMEM);

    static cudaStream_t s2 = nullptr;
    static cudaEvent_t evFork = nullptr, evJoin = nullptr;
    if (!s2) {
        cudaStreamCreateWithFlags(&s2, cudaStreamNonBlocking);
        cudaEventCreateWithFlags(&evFork, cudaEventDisableTiming);
        cudaEventCreateWithFlags(&evJoin, cudaEventDisableTiming);
    }

    // 1) transpose + LN1 + LN2 (coalesced, main stream)
    ln_tile_kernel<<<dim3(HW_/32, B_), 256, LN_SMEM>>>(x, ln1_g, ln1_b, ln2_g, ln2_b, t, a, f);

    // fork: FF branch on s2 (depends only on f)
    cudaEventRecord(evFork, 0);
    cudaStreamWaitEvent(s2, evFork, 0);

    // FF branch
    tgemm_kernel<<<dim3(HID/128, MTOT/128), 256, TG_SMEM, s2>>>(f, w_ff1, g,
        MTOT, HID, C_, b_ff1, nullptr, 1);
    tgemm_kernel<<<dim3(C_/128, MTOT/128), 256, TG_SMEM, s2>>>(g, w_ff2, ff,
        MTOT, C_, HID, b_ff2, nullptr, 0);
    cudaEventRecord(evJoin, s2);

    // Attention branch (main stream)
    tgemm_kernel<<<dim3(3*INNER/128, MTOT/128), 256, TG_SMEM>>>(a, w_qkv, qkv,
        MTOT, 3*INNER, C_, nullptr, nullptr, 0);
    attn_mma_kernel<<<B_*HEADS, 256, ATT_SMEM_B>>>(qkv, bias_table, o);
    tgemm_kernel<<<dim3(C_/128, MTOT/128), 256, TG_SMEM>>>(o, w_out, s1,
        MTOT, C_, INNER, b_out, t, 0);

    // join, then fused add + transpose
    cudaStreamWaitEvent(0, evJoin, 0);
    transpose_add_kernel<<<dim3(C_/32, HW_/32, B_), dim3(32, 8)>>>(s1, ff, (float*)d_out);
}

// round 8
// speedup vs baseline: 1.4533x; 1.4533x over previous
#include <cuda_runtime.h>
#include <cuda_fp16.h>
#include <math.h>

// ---------------- problem constants ----------------
#define B_   64
#define C_   384
#define HW_  256            // n = H*W
#define MTOT (B_*HW_)       // 16384
#define HEADS 8
#define DHEAD 32
#define INNER (HEADS*DHEAD) // 256
#define HID   (4*C_)        // 1536

// ---------------- device scratch (allocation-free rule) ----------------
__device__ float g_t  [MTOT*C_];
__device__ float g_a  [MTOT*C_];
__device__ float g_f  [MTOT*C_];
__device__ float g_qkv[MTOT*3*INNER];
__device__ float g_o  [MTOT*INNER];
__device__ float g_s1 [MTOT*C_];
__device__ float g_ff [MTOT*C_];
__device__ float g_g  [MTOT*HID];

// ---------------- tiled transpose + dual LayerNorm (coalesced, from R7) ----------------
#define LN_SMEM (C_*33*4)
__global__ __launch_bounds__(256)
void ln_tile_kernel(const float* __restrict__ x,
                    const float* __restrict__ g1, const float* __restrict__ b1,
                    const float* __restrict__ g2, const float* __restrict__ b2,
                    float* __restrict__ t, float* __restrict__ a, float* __restrict__ f)
{
    extern __shared__ float tile[];   // [C_][33]
    const int tid = threadIdx.x;
    const int p0  = blockIdx.x * 32;
    const int b   = blockIdx.y;

    #pragma unroll
    for (int i = 0; i < 12; i++) {
        int l  = tid + i*256;
        int c  = l >> 3;
        int p4 = (l & 7) * 4;
        float4 v = *(const float4*)&x[((size_t)b*C_ + c)*HW_ + p0 + p4];
        tile[c*33 + p4 + 0] = v.x;
        tile[c*33 + p4 + 1] = v.y;
        tile[c*33 + p4 + 2] = v.z;
        tile[c*33 + p4 + 3] = v.w;
    }
    __syncthreads();

    const int jj = tid & 7;
    const int pp = tid >> 3;

    float vals[48];
    #pragma unroll
    for (int i = 0; i < 12; i++) {
        int c4 = (jj + 8*i) * 4;
        #pragma unroll
        for (int k = 0; k < 4; k++)
            vals[i*4 + k] = tile[(c4 + k)*33 + pp];
    }

    float s = 0.f;
    #pragma unroll
    for (int v = 0; v < 48; v++) s += vals[v];
    #pragma unroll
    for (int o = 4; o; o >>= 1) s += __shfl_down_sync(0xffffffffu, s, o, 8);
    float mean = __shfl_sync(0xffffffffu, s, 0, 8) * (1.f/384.f);

    float sq = 0.f;
    #pragma unroll
    for (int v = 0; v < 48; v++) { float d = vals[v] - mean; sq += d*d; }
    #pragma unroll
    for (int o = 4; o; o >>= 1) sq += __shfl_down_sync(0xffffffffu, sq, o, 8);
    float rstd = rsqrtf(__shfl_sync(0xffffffffu, sq, 0, 8) * (1.f/384.f) + 1e-5f);

    const size_t base = (size_t)(b*HW_ + p0 + pp) * C_;
    #pragma unroll
    for (int i = 0; i < 12; i++) {
        int c4 = (jj + 8*i) * 4;
        float4 tv = make_float4(vals[i*4+0], vals[i*4+1], vals[i*4+2], vals[i*4+3]);
        *(float4*)&t[base + c4] = tv;
        float4 G1 = *(const float4*)&g1[c4];
        float4 B1 = *(const float4*)&b1[c4];
        float4 G2 = *(const float4*)&g2[c4];
        float4 B2 = *(const float4*)&b2[c4];
        float n0 = (tv.x - mean)*rstd, n1 = (tv.y - mean)*rstd;
        float n2 = (tv.z - mean)*rstd, n3 = (tv.w - mean)*rstd;
        *(float4*)&a[base + c4] = make_float4(n0*G1.x+B1.x, n1*G1.y+B1.y, n2*G1.z+B1.z, n3*G1.w+B1.w);
        *(float4*)&f[base + c4] = make_float4(n0*G2.x+B2.x, n1*G2.y+B2.y, n2*G2.z+B2.z, n3*G2.w+B2.w);
    }
}

// ---------------- tf32 tensor-core GEMM (exact R6 version: static smem, 2-stage) ----------------
__global__ __launch_bounds__(256, 2)
void tgemm_kernel(const float* __restrict__ A, const float* __restrict__ Bm,
                  float* __restrict__ C, int M, int N, int K,
                  const float* __restrict__ bias, const float* __restrict__ add,
                  int do_gelu)
{
    __shared__ float As[2][128][20];
    __shared__ float Bs[2][16][136];

    const int tid  = threadIdx.x;
    const int warp = tid >> 5;
    const int lane = tid & 31;
    const int g    = lane >> 2;
    const int t4   = lane & 3;

    const int brow = blockIdx.y * 128;
    const int bcol = blockIdx.x * 128;

    const int wr = warp & 3;
    const int wc = warp >> 2;

    float acc[2][8][4];
    #pragma unroll
    for (int mi = 0; mi < 2; mi++)
        #pragma unroll
        for (int ni = 0; ni < 8; ni++)
            #pragma unroll
            for (int e = 0; e < 4; e++) acc[mi][ni][e] = 0.f;

    const int a_row = tid >> 2;
    const int a_c4  = (tid & 3) * 4;
    const int b_kr  = tid >> 5;
    const int b_c4  = (tid & 31) * 4;

    auto issue = [&](int kt, int buf) {
        int k0 = kt * 16;
        #pragma unroll
        for (int q = 0; q < 2; q++) {
            const float* src = &A[(size_t)(brow + a_row + q*64)*K + k0 + a_c4];
            unsigned dst = (unsigned)__cvta_generic_to_shared(&As[buf][a_row + q*64][a_c4]);
            asm volatile("cp.async.cg.shared.global [%0], [%1], 16;" :: "r"(dst), "l"(src));
        }
        #pragma unroll
        for (int q = 0; q < 2; q++) {
            const float* src = &Bm[(size_t)(k0 + b_kr + q*8)*N + bcol + b_c4];
            unsigned dst = (unsigned)__cvta_generic_to_shared(&Bs[buf][b_kr + q*8][b_c4]);
            asm volatile("cp.async.cg.shared.global [%0], [%1], 16;" :: "r"(dst), "l"(src));
        }
        asm volatile("cp.async.commit_group;");
    };

    auto compute = [&](int buf) {
        #pragma unroll
        for (int ch = 0; ch < 2; ch++) {
            unsigned a[2][4];
            #pragma unroll
            for (int mi = 0; mi < 2; mi++) {
                int r0 = wr*32 + mi*16 + g;
                a[mi][0] = __float_as_uint(As[buf][r0    ][ch*8 + t4    ]);
                a[mi][1] = __float_as_uint(As[buf][r0 + 8][ch*8 + t4    ]);
                a[mi][2] = __float_as_uint(As[buf][r0    ][ch*8 + t4 + 4]);
                a[mi][3] = __float_as_uint(As[buf][r0 + 8][ch*8 + t4 + 4]);
            }
            #pragma unroll
            for (int ni = 0; ni < 8; ni++) {
                int col = wc*64 + ni*8 + g;
                unsigned b0 = __float_as_uint(Bs[buf][ch*8 + t4    ][col]);
                unsigned b1 = __float_as_uint(Bs[buf][ch*8 + t4 + 4][col]);
                #pragma unroll
                for (int mi = 0; mi < 2; mi++) {
                    asm volatile(
                        "mma.sync.aligned.m16n8k8.row.col.f32.tf32.tf32.f32 "
                        "{%0,%1,%2,%3},{%4,%5,%6,%7},{%8,%9},{%0,%1,%2,%3};"
                        : "+f"(acc[mi][ni][0]), "+f"(acc[mi][ni][1]),
                          "+f"(acc[mi][ni][2]), "+f"(acc[mi][ni][3])
                        : "r"(a[mi][0]), "r"(a[mi][1]), "r"(a[mi][2]), "r"(a[mi][3]),
                          "r"(b0), "r"(b1));
                }
            }
        }
    };

    const int nkt = K >> 4;
    issue(0, 0);
    for (int kt = 0; kt < nkt; kt++) {
        if (kt + 1 < nkt) {
            issue(kt + 1, (kt + 1) & 1);
            asm volatile("cp.async.wait_group 1;");
        } else {
            asm volatile("cp.async.wait_group 0;");
        }
        __syncthreads();
        compute(kt & 1);
        __syncthreads();
    }

    #pragma unroll
    for (int mi = 0; mi < 2; mi++) {
        int r0 = brow + wr*32 + mi*16 + g;
        #pragma unroll
        for (int ni = 0; ni < 8; ni++) {
            int col = bcol + wc*64 + ni*8 + 2*t4;
            float v0 = acc[mi][ni][0];
            float v1 = acc[mi][ni][1];
            float v2 = acc[mi][ni][2];
            float v3 = acc[mi][ni][3];
            if (bias) {
                float bz0 = bias[col], bz1 = bias[col+1];
                v0 += bz0; v1 += bz1; v2 += bz0; v3 += bz1;
            }
            if (do_gelu) {
                v0 = 0.5f*v0*(1.f + erff(v0*0.70710678118654752f));
                v1 = 0.5f*v1*(1.f + erff(v1*0.70710678118654752f));
                v2 = 0.5f*v2*(1.f + erff(v2*0.70710678118654752f));
                v3 = 0.5f*v3*(1.f + erff(v3*0.70710678118654752f));
            }
            if (add) {
                float2 a0 = *(const float2*)&add[(size_t)r0*N + col];
                float2 a1 = *(const float2*)&add[(size_t)(r0+8)*N + col];
                v0 += a0.x; v1 += a0.y; v2 += a1.x; v3 += a1.y;
            }
            *(float2*)&C[(size_t)r0*N + col]     = make_float2(v0, v1);
            *(float2*)&C[(size_t)(r0+8)*N + col] = make_float2(v2, v3);
        }
    }
}

// ---------------- tensor-core attention (unchanged from R5) ----------------
#define ATT_KS_F   (256*36)
#define ATT_VS_H   (32*264)
#define ATT_SMEM_B (ATT_KS_F*4 + ATT_VS_H*2 + 961*4)

__global__ void attn_mma_kernel(const float* __restrict__ qkv,
                                const float* __restrict__ bias_table,
                                float* __restrict__ o)
{
    extern __shared__ float sm[];
    float*  ks  = sm;
    __half* vs  = (__half*)(sm + ATT_KS_F);
    float*  bsh = sm + ATT_KS_F + ATT_VS_H/2;

    const int b = blockIdx.x >> 3, h = blockIdx.x & 7;
    const int tid = threadIdx.x, warp = tid >> 5, lane = tid & 31;
    const int g = lane >> 2, t4 = lane & 3;
    const float* base = qkv + (size_t)b * HW_ * 768;

    for (int l = tid; l < 2048; l += 256) {
        int j = l >> 3, c4 = (l & 7) * 4;
        float4 kv = *(const float4*)&base[(size_t)j*768 + 256 + h*32 + c4];
        *(float4*)&ks[j*36 + c4] = kv;
        float4 vv = *(const float4*)&base[(size_t)j*768 + 512 + h*32 + c4];
        vs[(c4+0)*264 + j] = __float2half(vv.x);
        vs[(c4+1)*264 + j] = __float2half(vv.y);
        vs[(c4+2)*264 + j] = __float2half(vv.z);
        vs[(c4+3)*264 + j] = __float2half(vv.w);
    }
    for (int l = tid; l < 961; l += 256) bsh[l] = bias_table[(size_t)l*8 + h];

    const float scale = 0.17677669529663688f;
    unsigned qa[2][4][4];
    #pragma unroll
    for (int mi = 0; mi < 2; mi++) {
        int r0 = warp*32 + mi*16 + g;
        const float* q0 = &base[(size_t)r0*768 + h*32];
        const float* q1 = &base[(size_t)(r0+8)*768 + h*32];
        #pragma unroll
        for (int k = 0; k < 4; k++) {
            qa[mi][k][0] = __float_as_uint(q0[k*8 + t4]     * scale);
            qa[mi][k][1] = __float_as_uint(q1[k*8 + t4]     * scale);
            qa[mi][k][2] = __float_as_uint(q0[k*8 + t4 + 4] * scale);
            qa[mi][k][3] = __float_as_uint(q1[k*8 + t4 + 4] * scale);
        }
    }

    int bb[2][2];
    #pragma unroll
    for (int mi = 0; mi < 2; mi++) {
        int i0 = warp*32 + mi*16 + g;
        bb[mi][0] = ((i0 >> 4) + 15)*31 + (i0 & 15) + 15;
        bb[mi][1] = (((i0+8) >> 4) + 15)*31 + ((i0+8) & 15) + 15;
    }
    __syncthreads();

    float acco[2][4][4];
    #pragma unroll
    for (int mi = 0; mi < 2; mi++)
        #pragma unroll
        for (int vn = 0; vn < 4; vn++)
            #pragma unroll
            for (int e = 0; e < 4; e++) acco[mi][vn][e] = 0.f;
    float rs[2][2] = {{0.f, 0.f}, {0.f, 0.f}};

    for (int j0 = 0; j0 < 256; j0 += 32) {
        float accs[2][4][4];
        #pragma unroll
        for (int mi = 0; mi < 2; mi++)
            #pragma unroll
            for (int ni = 0; ni < 4; ni++)
                #pragma unroll
                for (int e = 0; e < 4; e++) accs[mi][ni][e] = 0.f;

        #pragma unroll
        for (int k = 0; k < 4; k++) {
            #pragma unroll
            for (int ni = 0; ni < 4; ni++) {
                unsigned kb0 = __float_as_uint(ks[(j0 + ni*8 + g)*36 + k*8 + t4]);
                unsigned kb1 = __float_as_uint(ks[(j0 + ni*8 + g)*36 + k*8 + t4 + 4]);
                #pragma unroll
                for (int mi = 0; mi < 2; mi++) {
                    asm volatile(
                        "mma.sync.aligned.m16n8k8.row.col.f32.tf32.tf32.f32 "
                        "{%0,%1,%2,%3},{%4,%5,%6,%7},{%8,%9},{%0,%1,%2,%3};"
                        : "+f"(accs[mi][ni][0]), "+f"(accs[mi][ni][1]),
                          "+f"(accs[mi][ni][2]), "+f"(accs[mi][ni][3])
                        : "r"(qa[mi][k][0]), "r"(qa[mi][k][1]),
                          "r"(qa[mi][k][2]), "r"(qa[mi][k][3]),
                          "r"(kb0), "r"(kb1));
                }
            }
        }

        unsigned pk[2][4][2];
        #pragma unroll
        for (int mi = 0; mi < 2; mi++) {
            #pragma unroll
            for (int ni = 0; ni < 4; ni++) {
                int j  = j0 + ni*8 + 2*t4;
                int o0 = (j >> 4)*31 + (j & 15);
                int o1 = ((j+1) >> 4)*31 + ((j+1) & 15);
                float p0 = __expf(accs[mi][ni][0] + bsh[bb[mi][0] - o0]);
                float p1 = __expf(accs[mi][ni][1] + bsh[bb[mi][0] - o1]);
                float p2 = __expf(accs[mi][ni][2] + bsh[bb[mi][1] - o0]);
                float p3 = __expf(accs[mi][ni][3] + bsh[bb[mi][1] - o1]);
                rs[mi][0] += p0 + p1;
                rs[mi][1] += p2 + p3;
                __half2 h01 = __floats2half2_rn(p0, p1);
                __half2 h23 = __floats2half2_rn(p2, p3);
                pk[mi][ni][0] = *(unsigned*)&h01;
                pk[mi][ni][1] = *(unsigned*)&h23;
            }
        }

        #pragma unroll
        for (int k = 0; k < 2; k++) {
            #pragma unroll
            for (int vn = 0; vn < 4; vn++) {
                unsigned vb0 = *(const unsigned*)&vs[(vn*8 + g)*264 + j0 + k*16 + 2*t4];
                unsigned vb1 = *(const unsigned*)&vs[(vn*8 + g)*264 + j0 + k*16 + 2*t4 + 8];
                #pragma unroll
                for (int mi = 0; mi < 2; mi++) {
                    asm volatile(
                        "mma.sync.aligned.m16n8k16.row.col.f32.f16.f16.f32 "
                        "{%0,%1,%2,%3},{%4,%5,%6,%7},{%8,%9},{%0,%1,%2,%3};"
                        : "+f"(acco[mi][vn][0]), "+f"(acco[mi][vn][1]),
                          "+f"(acco[mi][vn][2]), "+f"(acco[mi][vn][3])
                        : "r"(pk[mi][2*k][0]), "r"(pk[mi][2*k][1]),
                          "r"(pk[mi][2*k+1][0]), "r"(pk[mi][2*k+1][1]),
                          "r"(vb0), "r"(vb1));
                }
            }
        }
    }

    #pragma unroll
    for (int mi = 0; mi < 2; mi++)
        #pragma unroll
        for (int r = 0; r < 2; r++) {
            float v = rs[mi][r];
            v += __shfl_xor_sync(0xffffffffu, v, 1);
            v += __shfl_xor_sync(0xffffffffu, v, 2);
            rs[mi][r] = 1.f / v;
        }

    #pragma unroll
    for (int mi = 0; mi < 2; mi++) {
        int r0 = warp*32 + mi*16 + g;
        #pragma unroll
        for (int vn = 0; vn < 4; vn++) {
            int col = h*32 + vn*8 + 2*t4;
            *(float2*)&o[((size_t)(b*HW_) + r0)*INNER + col] =
                make_float2(acco[mi][vn][0]*rs[mi][0], acco[mi][vn][1]*rs[mi][0]);
            *(float2*)&o[((size_t)(b*HW_) + r0 + 8)*INNER + col] =
                make_float2(acco[mi][vn][2]*rs[mi][1], acco[mi][vn][3]*rs[mi][1]);
        }
    }
}

// ---------------- fused join: out[B,C,H,W] = transpose(s1 + ff) ----------------
__global__ void transpose_add_kernel(const float* __restrict__ s1,
                                     const float* __restrict__ ff,
                                     float* __restrict__ out)
{
    __shared__ float tile[32][33];
    int b  = blockIdx.z;
    int c0 = blockIdx.x * 32;
    int p0 = blockIdx.y * 32;

    for (int i = threadIdx.y; i < 32; i += 8) {
        size_t idx = (size_t)(b*HW_ + p0 + i)*C_ + c0 + threadIdx.x;
        tile[i][threadIdx.x] = s1[idx] + ff[idx];
    }
    __syncthreads();
    float* ob = out + (size_t)b * C_ * HW_;
    for (int i = threadIdx.y; i < 32; i += 8)
        ob[(size_t)(c0 + i)*HW_ + p0 + threadIdx.x] = tile[threadIdx.x][i];
}

// ---------------- launch ----------------
extern "C" void kernel_launch(void* const* d_in, const int* in_sizes, int n_in,
                              void* d_out, int out_size)
{
    const float* x          = (const float*)d_in[0];
    const float* ln1_g      = (const float*)d_in[1];
    const float* ln1_b      = (const float*)d_in[2];
    const float* w_qkv      = (const float*)d_in[3];
    const float* bias_table = (const float*)d_in[4];
    const float* w_out      = (const float*)d_in[5];
    const float* b_out      = (const float*)d_in[6];
    const float* ln2_g      = (const float*)d_in[7];
    const float* ln2_b      = (const float*)d_in[8];
    const float* w_ff1      = (const float*)d_in[9];
    const float* b_ff1      = (const float*)d_in[10];
    const float* w_ff2      = (const float*)d_in[11];
    const float* b_ff2      = (const float*)d_in[12];

    float *t, *a, *f, *qkv, *o, *s1, *ff, *g;
    cudaGetSymbolAddress((void**)&t,   g_t);
    cudaGetSymbolAddress((void**)&a,   g_a);
    cudaGetSymbolAddress((void**)&f,   g_f);
    cudaGetSymbolAddress((void**)&qkv, g_qkv);
    cudaGetSymbolAddress((void**)&o,   g_o);
    cudaGetSymbolAddress((void**)&s1,  g_s1);
    cudaGetSymbolAddress((void**)&ff,  g_ff);
    cudaGetSymbolAddress((void**)&g,   g_g);

    cudaFuncSetAttribute(attn_mma_kernel, cudaFuncAttributeMaxDynamicSharedMemorySize, ATT_SMEM_B);
    cudaFuncSetAttribute(ln_tile_kernel,  cudaFuncAttributeMaxDynamicSharedMemorySize, LN_SMEM);

    static cudaStream_t s2 = nullptr;
    static cudaEvent_t evFork = nullptr, evJoin = nullptr;
    if (!s2) {
        cudaStreamCreateWithFlags(&s2, cudaStreamNonBlocking);
        cudaEventCreateWithFlags(&evFork, cudaEventDisableTiming);
        cudaEventCreateWithFlags(&evJoin, cudaEventDisableTiming);
    }

    // 1) transpose + LN1 + LN2 (coalesced, main stream)
    ln_tile_kernel<<<dim3(HW_/32, B_), 256, LN_SMEM>>>(x, ln1_g, ln1_b, ln2_g, ln2_b, t, a, f);

    // fork: FF branch on s2 (depends only on f)
    cudaEventRecord(evFork, 0);
    cudaStreamWaitEvent(s2, evFork, 0);

    // FF branch
    tgemm_kernel<<<dim3(HID/128, MTOT/128), 256, 0, s2>>>(f, w_ff1, g,
        MTOT, HID, C_, b_ff1, nullptr, 1);
    tgemm_kernel<<<dim3(C_/128, MTOT/128), 256, 0, s2>>>(g, w_ff2, ff,
        MTOT, C_, HID, b_ff2, nullptr, 0);
    cudaEventRecord(evJoin, s2);

    // Attention branch (main stream)
    tgemm_kernel<<<dim3(3*INNER/128, MTOT/128), 256>>>(a, w_qkv, qkv,
        MTOT, 3*INNER, C_, nullptr, nullptr, 0);
    attn_mma_kernel<<<B_*HEADS, 256, ATT_SMEM_B>>>(qkv, bias_table, o);
    tgemm_kernel<<<dim3(C_/128, MTOT/128), 256>>>(o, w_out, s1,
        MTOT, C_, INNER, b_out, t, 0);

    // join, then fused add + transpose
    cudaStreamWaitEvent(0, evJoin, 0);
    transpose_add_kernel<<<dim3(C_/32, HW_/32, B_), dim3(32, 8)>>>(s1, ff, (float*)d_out);
}

// round 9
// speedup vs baseline: 2.1463x; 1.4769x over previous
#include <cuda_runtime.h>
#include <cuda_fp16.h>
#include <math.h>

// ---------------- problem constants ----------------
#define B_   64
#define C_   384
#define HW_  256            // n = H*W
#define MTOT (B_*HW_)       // 16384
#define HEADS 8
#define DHEAD 32
#define INNER (HEADS*DHEAD) // 256
#define HID   (4*C_)        // 1536

// ---------------- device scratch (allocation-free rule) ----------------
__device__ float g_t  [MTOT*C_];
__device__ float g_qkv[MTOT*3*INNER];
__device__ float g_s1 [MTOT*C_];
__device__ float g_ff [MTOT*C_];
__device__ __align__(16) __half g_ah [MTOT*C_];
__device__ __align__(16) __half g_fh [MTOT*C_];
__device__ __align__(16) __half g_oh [MTOT*INNER];
__device__ __align__(16) __half g_gh [MTOT*HID];
__device__ __align__(16) __half g_wqkvh[C_*3*INNER];
__device__ __align__(16) __half g_wouth[INNER*C_];
__device__ __align__(16) __half g_wff1h[C_*HID];
__device__ __align__(16) __half g_wff2h[HID*C_];

// ---------------- fp32 -> fp16 converter (weights) ----------------
__global__ void f2h_kernel(const float* __restrict__ src, __half* __restrict__ dst)
{
    int i = (blockIdx.x*256 + threadIdx.x)*4;
    float4 v = *(const float4*)&src[i];
    __half2 h01 = __floats2half2_rn(v.x, v.y);
    __half2 h23 = __floats2half2_rn(v.z, v.w);
    *(uint2*)&dst[i] = make_uint2(*(unsigned*)&h01, *(unsigned*)&h23);
}

// ---------------- tiled transpose + dual LayerNorm (coalesced; fp16 a/f) ----------------
#define LN_SMEM (C_*33*4)
__global__ __launch_bounds__(256)
void ln_tile_kernel(const float* __restrict__ x,
                    const float* __restrict__ g1, const float* __restrict__ b1,
                    const float* __restrict__ g2, const float* __restrict__ b2,
                    float* __restrict__ t, __half* __restrict__ a, __half* __restrict__ f)
{
    extern __shared__ float tile[];   // [C_][33]
    const int tid = threadIdx.x;
    const int p0  = blockIdx.x * 32;
    const int b   = blockIdx.y;

    #pragma unroll
    for (int i = 0; i < 12; i++) {
        int l  = tid + i*256;
        int c  = l >> 3;
        int p4 = (l & 7) * 4;
        float4 v = *(const float4*)&x[((size_t)b*C_ + c)*HW_ + p0 + p4];
        tile[c*33 + p4 + 0] = v.x;
        tile[c*33 + p4 + 1] = v.y;
        tile[c*33 + p4 + 2] = v.z;
        tile[c*33 + p4 + 3] = v.w;
    }
    __syncthreads();

    const int jj = tid & 7;
    const int pp = tid >> 3;

    float vals[48];
    #pragma unroll
    for (int i = 0; i < 12; i++) {
        int c4 = (jj + 8*i) * 4;
        #pragma unroll
        for (int k = 0; k < 4; k++)
            vals[i*4 + k] = tile[(c4 + k)*33 + pp];
    }

    float s = 0.f;
    #pragma unroll
    for (int v = 0; v < 48; v++) s += vals[v];
    #pragma unroll
    for (int o = 4; o; o >>= 1) s += __shfl_down_sync(0xffffffffu, s, o, 8);
    float mean = __shfl_sync(0xffffffffu, s, 0, 8) * (1.f/384.f);

    float sq = 0.f;
    #pragma unroll
    for (int v = 0; v < 48; v++) { float d = vals[v] - mean; sq += d*d; }
    #pragma unroll
    for (int o = 4; o; o >>= 1) sq += __shfl_down_sync(0xffffffffu, sq, o, 8);
    float rstd = rsqrtf(__shfl_sync(0xffffffffu, sq, 0, 8) * (1.f/384.f) + 1e-5f);

    const size_t base = (size_t)(b*HW_ + p0 + pp) * C_;
    #pragma unroll
    for (int i = 0; i < 12; i++) {
        int c4 = (jj + 8*i) * 4;
        float4 tv = make_float4(vals[i*4+0], vals[i*4+1], vals[i*4+2], vals[i*4+3]);
        *(float4*)&t[base + c4] = tv;
        float4 G1 = *(const float4*)&g1[c4];
        float4 B1 = *(const float4*)&b1[c4];
        float4 G2 = *(const float4*)&g2[c4];
        float4 B2 = *(const float4*)&b2[c4];
        float n0 = (tv.x - mean)*rstd, n1 = (tv.y - mean)*rstd;
        float n2 = (tv.z - mean)*rstd, n3 = (tv.w - mean)*rstd;
        __half2 a01 = __floats2half2_rn(n0*G1.x+B1.x, n1*G1.y+B1.y);
        __half2 a23 = __floats2half2_rn(n2*G1.z+B1.z, n3*G1.w+B1.w);
        __half2 f01 = __floats2half2_rn(n0*G2.x+B2.x, n1*G2.y+B2.y);
        __half2 f23 = __floats2half2_rn(n2*G2.z+B2.z, n3*G2.w+B2.w);
        *(uint2*)&a[base + c4] = make_uint2(*(unsigned*)&a01, *(unsigned*)&a23);
        *(uint2*)&f[base + c4] = make_uint2(*(unsigned*)&f01, *(unsigned*)&f23);
    }
}

// ---------------- fp16 tensor-core GEMM ----------------
// C[M,N] = A[M,K] @ B[K,N]  (+bias) (gelu) (+add); A,B fp16, acc fp32.
// BM=128 BN=128 BK=32, 256 threads (8 warps 4x2), warp tile 32x64 (m16n8k16).
// cp.async coalesced fills; ldmatrix fragment loads, conflict-free pitches
// (As pitch 40 halves: 20m mod 32 permutes; Bs pitch 136: 4k mod 32 permutes).
__global__ __launch_bounds__(256, 2)
void hgemm_kernel(const __half* __restrict__ A, const __half* __restrict__ Bm,
                  void* __restrict__ Cout, int M, int N, int K,
                  const float* __restrict__ bias, const float* __restrict__ add,
                  int do_gelu, int out_half)
{
    __shared__ __half As[2][128][40];
    __shared__ __half Bs[2][32][136];

    const int tid  = threadIdx.x;
    const int warp = tid >> 5;
    const int lane = tid & 31;
    const int g    = lane >> 2;
    const int t4   = lane & 3;

    const int brow = blockIdx.y * 128;
    const int bcol = blockIdx.x * 128;

    const int wr = warp & 3;     // rows wr*32
    const int wc = warp >> 2;    // cols wc*64

    float acc[2][8][4];
    #pragma unroll
    for (int mi = 0; mi < 2; mi++)
        #pragma unroll
        for (int ni = 0; ni < 8; ni++)
            #pragma unroll
            for (int e = 0; e < 4; e++) acc[mi][ni][e] = 0.f;

    // loaders
    const int a_row = tid >> 1;           // 0..127
    const int a_k16 = (tid & 1) * 16;     // halves
    const int b_row = tid >> 3;           // 0..31
    const int b_c16 = (tid & 7) * 16;     // halves

    auto issue = [&](int kt, int buf) {
        int k0 = kt * 32;
        {
            const __half* src = &A[(size_t)(brow + a_row)*K + k0 + a_k16];
            unsigned dst = (unsigned)__cvta_generic_to_shared(&As[buf][a_row][a_k16]);
            asm volatile("cp.async.cg.shared.global [%0], [%1], 16;" :: "r"(dst), "l"(src));
            asm volatile("cp.async.cg.shared.global [%0], [%1], 16;" :: "r"(dst+16), "l"(src+8));
        }
        {
            const __half* src = &Bm[(size_t)(k0 + b_row)*N + bcol + b_c16];
            unsigned dst = (unsigned)__cvta_generic_to_shared(&Bs[buf][b_row][b_c16]);
            asm volatile("cp.async.cg.shared.global [%0], [%1], 16;" :: "r"(dst), "l"(src));
            asm volatile("cp.async.cg.shared.global [%0], [%1], 16;" :: "r"(dst+16), "l"(src+8));
        }
        asm volatile("cp.async.commit_group;");
    };

    const int lm_r   = lane & 7;          // row within 8x8 matrix
    const int lm_m01 = (lane >> 3) & 1;   // +8 row selector
    const int lm_m23 = lane >> 4;         // +8 col/k selector

    auto compute = [&](int buf) {
        #pragma unroll
        for (int sub = 0; sub < 2; sub++) {
            const int koff = sub * 16;
            // A fragments: 2x ldmatrix.x4
            unsigned a[2][4];
            #pragma unroll
            for (int mi = 0; mi < 2; mi++) {
                unsigned addr = (unsigned)__cvta_generic_to_shared(
                    &As[buf][wr*32 + mi*16 + lm_m01*8 + lm_r][koff + lm_m23*8]);
                asm volatile("ldmatrix.sync.aligned.m8n8.x4.shared.b16 {%0,%1,%2,%3}, [%4];"
                    : "=r"(a[mi][0]), "=r"(a[mi][1]), "=r"(a[mi][2]), "=r"(a[mi][3])
                    : "r"(addr));
            }
            // B fragments: 4x ldmatrix.x4.trans (each covers 2 ni blocks)
            unsigned bfr[8][2];
            #pragma unroll
            for (int p = 0; p < 4; p++) {
                unsigned addr = (unsigned)__cvta_generic_to_shared(
                    &Bs[buf][koff + lm_m01*8 + lm_r][wc*64 + p*16 + lm_m23*8]);
                unsigned r0, r1, r2, r3;
                asm volatile("ldmatrix.sync.aligned.m8n8.x4.trans.shared.b16 {%0,%1,%2,%3}, [%4];"
                    : "=r"(r0), "=r"(r1), "=r"(r2), "=r"(r3)
                    : "r"(addr));
                bfr[2*p][0] = r0;  bfr[2*p][1] = r1;
                bfr[2*p+1][0] = r2; bfr[2*p+1][1] = r3;
            }
            #pragma unroll
            for (int ni = 0; ni < 8; ni++)
                #pragma unroll
                for (int mi = 0; mi < 2; mi++) {
                    asm volatile(
                        "mma.sync.aligned.m16n8k16.row.col.f32.f16.f16.f32 "
                        "{%0,%1,%2,%3},{%4,%5,%6,%7},{%8,%9},{%0,%1,%2,%3};"
                        : "+f"(acc[mi][ni][0]), "+f"(acc[mi][ni][1]),
                          "+f"(acc[mi][ni][2]), "+f"(acc[mi][ni][3])
                        : "r"(a[mi][0]), "r"(a[mi][1]), "r"(a[mi][2]), "r"(a[mi][3]),
                          "r"(bfr[ni][0]), "r"(bfr[ni][1]));
                }
        }
    };

    const int nkt = K >> 5;
    issue(0, 0);
    for (int kt = 0; kt < nkt; kt++) {
        if (kt + 1 < nkt) {
            issue(kt + 1, (kt + 1) & 1);
            asm volatile("cp.async.wait_group 1;");
        } else {
            asm volatile("cp.async.wait_group 0;");
        }
        __syncthreads();
        compute(kt & 1);
        __syncthreads();
    }

    // ---- epilogue ----
    #pragma unroll
    for (int mi = 0; mi < 2; mi++) {
        int r0 = brow + wr*32 + mi*16 + g;
        #pragma unroll
        for (int ni = 0; ni < 8; ni++) {
            int col = bcol + wc*64 + ni*8 + 2*t4;
            float v0 = acc[mi][ni][0];
            float v1 = acc[mi][ni][1];
            float v2 = acc[mi][ni][2];
            float v3 = acc[mi][ni][3];
            if (bias) {
                float bz0 = bias[col], bz1 = bias[col+1];
                v0 += bz0; v1 += bz1; v2 += bz0; v3 += bz1;
            }
            if (do_gelu) {
                v0 = 0.5f*v0*(1.f + erff(v0*0.70710678118654752f));
                v1 = 0.5f*v1*(1.f + erff(v1*0.70710678118654752f));
                v2 = 0.5f*v2*(1.f + erff(v2*0.70710678118654752f));
                v3 = 0.5f*v3*(1.f + erff(v3*0.70710678118654752f));
            }
            if (add) {
                float2 a0 = *(const float2*)&add[(size_t)r0*N + col];
                float2 a1 = *(const float2*)&add[(size_t)(r0+8)*N + col];
                v0 += a0.x; v1 += a0.y; v2 += a1.x; v3 += a1.y;
            }
            if (out_half) {
                __half* Ch = (__half*)Cout;
                __half2 h01 = __floats2half2_rn(v0, v1);
                __half2 h23 = __floats2half2_rn(v2, v3);
                *(unsigned*)&Ch[(size_t)r0*N + col]     = *(unsigned*)&h01;
                *(unsigned*)&Ch[(size_t)(r0+8)*N + col] = *(unsigned*)&h23;
            } else {
                float* C = (float*)Cout;
                *(float2*)&C[(size_t)r0*N + col]     = make_float2(v0, v1);
                *(float2*)&C[(size_t)(r0+8)*N + col] = make_float2(v2, v3);
            }
        }
    }
}

// ---------------- tensor-core attention (R5; o output now fp16) ----------------
#define ATT_KS_F   (256*36)
#define ATT_VS_H   (32*264)
#define ATT_SMEM_B (ATT_KS_F*4 + ATT_VS_H*2 + 961*4)

__global__ void attn_mma_kernel(const float* __restrict__ qkv,
                                const float* __restrict__ bias_table,
                                __half* __restrict__ o)
{
    extern __shared__ float sm[];
    float*  ks  = sm;
    __half* vs  = (__half*)(sm + ATT_KS_F);
    float*  bsh = sm + ATT_KS_F + ATT_VS_H/2;

    const int b = blockIdx.x >> 3, h = blockIdx.x & 7;
    const int tid = threadIdx.x, warp = tid >> 5, lane = tid & 31;
    const int g = lane >> 2, t4 = lane & 3;
    const float* base = qkv + (size_t)b * HW_ * 768;

    for (int l = tid; l < 2048; l += 256) {
        int j = l >> 3, c4 = (l & 7) * 4;
        float4 kv = *(const float4*)&base[(size_t)j*768 + 256 + h*32 + c4];
        *(float4*)&ks[j*36 + c4] = kv;
        float4 vv = *(const float4*)&base[(size_t)j*768 + 512 + h*32 + c4];
        vs[(c4+0)*264 + j] = __float2half(vv.x);
        vs[(c4+1)*264 + j] = __float2half(vv.y);
        vs[(c4+2)*264 + j] = __float2half(vv.z);
        vs[(c4+3)*264 + j] = __float2half(vv.w);
    }
    for (int l = tid; l < 961; l += 256) bsh[l] = bias_table[(size_t)l*8 + h];

    const float scale = 0.17677669529663688f;
    unsigned qa[2][4][4];
    #pragma unroll
    for (int mi = 0; mi < 2; mi++) {
        int r0 = warp*32 + mi*16 + g;
        const float* q0 = &base[(size_t)r0*768 + h*32];
        const float* q1 = &base[(size_t)(r0+8)*768 + h*32];
        #pragma unroll
        for (int k = 0; k < 4; k++) {
            qa[mi][k][0] = __float_as_uint(q0[k*8 + t4]     * scale);
            qa[mi][k][1] = __float_as_uint(q1[k*8 + t4]     * scale);
            qa[mi][k][2] = __float_as_uint(q0[k*8 + t4 + 4] * scale);
            qa[mi][k][3] = __float_as_uint(q1[k*8 + t4 + 4] * scale);
        }
    }

    int bb[2][2];
    #pragma unroll
    for (int mi = 0; mi < 2; mi++) {
        int i0 = warp*32 + mi*16 + g;
        bb[mi][0] = ((i0 >> 4) + 15)*31 + (i0 & 15) + 15;
        bb[mi][1] = (((i0+8) >> 4) + 15)*31 + ((i0+8) & 15) + 15;
    }
    __syncthreads();

    float acco[2][4][4];
    #pragma unroll
    for (int mi = 0; mi < 2; mi++)
        #pragma unroll
        for (int vn = 0; vn < 4; vn++)
            #pragma unroll
            for (int e = 0; e < 4; e++) acco[mi][vn][e] = 0.f;
    float rs[2][2] = {{0.f, 0.f}, {0.f, 0.f}};

    for (int j0 = 0; j0 < 256; j0 += 32) {
        float accs[2][4][4];
        #pragma unroll
        for (int mi = 0; mi < 2; mi++)
            #pragma unroll
            for (int ni = 0; ni < 4; ni++)
                #pragma unroll
                for (int e = 0; e < 4; e++) accs[mi][ni][e] = 0.f;

        #pragma unroll
        for (int k = 0; k < 4; k++) {
            #pragma unroll
            for (int ni = 0; ni < 4; ni++) {
                unsigned kb0 = __float_as_uint(ks[(j0 + ni*8 + g)*36 + k*8 + t4]);
                unsigned kb1 = __float_as_uint(ks[(j0 + ni*8 + g)*36 + k*8 + t4 + 4]);
                #pragma unroll
                for (int mi = 0; mi < 2; mi++) {
                    asm volatile(
                        "mma.sync.aligned.m16n8k8.row.col.f32.tf32.tf32.f32 "
                        "{%0,%1,%2,%3},{%4,%5,%6,%7},{%8,%9},{%0,%1,%2,%3};"
                        : "+f"(accs[mi][ni][0]), "+f"(accs[mi][ni][1]),
                          "+f"(accs[mi][ni][2]), "+f"(accs[mi][ni][3])
                        : "r"(qa[mi][k][0]), "r"(qa[mi][k][1]),
                          "r"(qa[mi][k][2]), "r"(qa[mi][k][3]),
                          "r"(kb0), "r"(kb1));
                }
            }
        }

        unsigned pk[2][4][2];
        #pragma unroll
        for (int mi = 0; mi < 2; mi++) {
            #pragma unroll
            for (int ni = 0; ni < 4; ni++) {
                int j  = j0 + ni*8 + 2*t4;
                int o0 = (j >> 4)*31 + (j & 15);
                int o1 = ((j+1) >> 4)*31 + ((j+1) & 15);
                float p0 = __expf(accs[mi][ni][0] + bsh[bb[mi][0] - o0]);
                float p1 = __expf(accs[mi][ni][1] + bsh[bb[mi][0] - o1]);
                float p2 = __expf(accs[mi][ni][2] + bsh[bb[mi][1] - o0]);
                float p3 = __expf(accs[mi][ni][3] + bsh[bb[mi][1] - o1]);
                rs[mi][0] += p0 + p1;
                rs[mi][1] += p2 + p3;
                __half2 h01 = __floats2half2_rn(p0, p1);
                __half2 h23 = __floats2half2_rn(p2, p3);
                pk[mi][ni][0] = *(unsigned*)&h01;
                pk[mi][ni][1] = *(unsigned*)&h23;
            }
        }

        #pragma unroll
        for (int k = 0; k < 2; k++) {
            #pragma unroll
            for (int vn = 0; vn < 4; vn++) {
                unsigned vb0 = *(const unsigned*)&vs[(vn*8 + g)*264 + j0 + k*16 + 2*t4];
                unsigned vb1 = *(const unsigned*)&vs[(vn*8 + g)*264 + j0 + k*16 + 2*t4 + 8];
                #pragma unroll
                for (int mi = 0; mi < 2; mi++) {
                    asm volatile(
                        "mma.sync.aligned.m16n8k16.row.col.f32.f16.f16.f32 "
                        "{%0,%1,%2,%3},{%4,%5,%6,%7},{%8,%9},{%0,%1,%2,%3};"
                        : "+f"(acco[mi][vn][0]), "+f"(acco[mi][vn][1]),
                          "+f"(acco[mi][vn][2]), "+f"(acco[mi][vn][3])
                        : "r"(pk[mi][2*k][0]), "r"(pk[mi][2*k][1]),
                          "r"(pk[mi][2*k+1][0]), "r"(pk[mi][2*k+1][1]),
                          "r"(vb0), "r"(vb1));
                }
            }
        }
    }

    #pragma unroll
    for (int mi = 0; mi < 2; mi++)
        #pragma unroll
        for (int r = 0; r < 2; r++) {
            float v = rs[mi][r];
            v += __shfl_xor_sync(0xffffffffu, v, 1);
            v += __shfl_xor_sync(0xffffffffu, v, 2);
            rs[mi][r] = 1.f / v;
        }

    #pragma unroll
    for (int mi = 0; mi < 2; mi++) {
        int r0 = warp*32 + mi*16 + g;
        #pragma unroll
        for (int vn = 0; vn < 4; vn++) {
            int col = h*32 + vn*8 + 2*t4;
            __half2 h0 = __floats2half2_rn(acco[mi][vn][0]*rs[mi][0], acco[mi][vn][1]*rs[mi][0]);
            __half2 h1 = __floats2half2_rn(acco[mi][vn][2]*rs[mi][1], acco[mi][vn][3]*rs[mi][1]);
            *(unsigned*)&o[((size_t)(b*HW_) + r0)*INNER + col]     = *(unsigned*)&h0;
            *(unsigned*)&o[((size_t)(b*HW_) + r0 + 8)*INNER + col] = *(unsigned*)&h1;
        }
    }
}

// ---------------- fused join: out[B,C,H,W] = transpose(s1 + ff) ----------------
__global__ void transpose_add_kernel(const float* __restrict__ s1,
                                     const float* __restrict__ ff,
                                     float* __restrict__ out)
{
    __shared__ float tile[32][33];
    int b  = blockIdx.z;
    int c0 = blockIdx.x * 32;
    int p0 = blockIdx.y * 32;

    for (int i = threadIdx.y; i < 32; i += 8) {
        size_t idx = (size_t)(b*HW_ + p0 + i)*C_ + c0 + threadIdx.x;
        tile[i][threadIdx.x] = s1[idx] + ff[idx];
    }
    __syncthreads();
    float* ob = out + (size_t)b * C_ * HW_;
    for (int i = threadIdx.y; i < 32; i += 8)
        ob[(size_t)(c0 + i)*HW_ + p0 + threadIdx.x] = tile[threadIdx.x][i];
}

// ---------------- launch ----------------
extern "C" void kernel_launch(void* const* d_in, const int* in_sizes, int n_in,
                              void* d_out, int out_size)
{
    const float* x          = (const float*)d_in[0];
    const float* ln1_g      = (const float*)d_in[1];
    const float* ln1_b      = (const float*)d_in[2];
    const float* w_qkv      = (const float*)d_in[3];
    const float* bias_table = (const float*)d_in[4];
    const float* w_out      = (const float*)d_in[5];
    const float* b_out      = (const float*)d_in[6];
    const float* ln2_g      = (const float*)d_in[7];
    const float* ln2_b      = (const float*)d_in[8];
    const float* w_ff1      = (const float*)d_in[9];
    const float* b_ff1      = (const float*)d_in[10];
    const float* w_ff2      = (const float*)d_in[11];
    const float* b_ff2      = (const float*)d_in[12];

    float *t, *qkv, *s1, *ff;
    __half *ah, *fh, *oh, *gh, *wqkvh, *wouth, *wff1h, *wff2h;
    cudaGetSymbolAddress((void**)&t,     g_t);
    cudaGetSymbolAddress((void**)&qkv,   g_qkv);
    cudaGetSymbolAddress((void**)&s1,    g_s1);
    cudaGetSymbolAddress((void**)&ff,    g_ff);
    cudaGetSymbolAddress((void**)&ah,    g_ah);
    cudaGetSymbolAddress((void**)&fh,    g_fh);
    cudaGetSymbolAddress((void**)&oh,    g_oh);
    cudaGetSymbolAddress((void**)&gh,    g_gh);
    cudaGetSymbolAddress((void**)&wqkvh, g_wqkvh);
    cudaGetSymbolAddress((void**)&wouth, g_wouth);
    cudaGetSymbolAddress((void**)&wff1h, g_wff1h);
    cudaGetSymbolAddress((void**)&wff2h, g_wff2h);

    cudaFuncSetAttribute(attn_mma_kernel, cudaFuncAttributeMaxDynamicSharedMemorySize, ATT_SMEM_B);
    cudaFuncSetAttribute(ln_tile_kernel,  cudaFuncAttributeMaxDynamicSharedMemorySize, LN_SMEM);

    static cudaStream_t s2 = nullptr;
    static cudaEvent_t ev0 = nullptr, evFork = nullptr, evJoin = nullptr;
    if (!s2) {
        cudaStreamCreateWithFlags(&s2, cudaStreamNonBlocking);
        cudaEventCreateWithFlags(&ev0,    cudaEventDisableTiming);
        cudaEventCreateWithFlags(&evFork, cudaEventDisableTiming);
        cudaEventCreateWithFlags(&evJoin, cudaEventDisableTiming);
    }

    // fork for weight conversion: s2 converts FF weights while s0 converts attn weights + LN
    cudaEventRecord(ev0, 0);
    cudaStreamWaitEvent(s2, ev0, 0);
    f2h_kernel<<<(C_*HID)/1024,  256, 0, s2>>>(w_ff1, wff1h);
    f2h_kernel<<<(HID*C_)/1024,  256, 0, s2>>>(w_ff2, wff2h);

    f2h_kernel<<<(C_*3*INNER)/1024, 256>>>(w_qkv, wqkvh);
    f2h_kernel<<<(INNER*C_)/1024,   256>>>(w_out, wouth);

    // transpose + LN1 + LN2 (fp16 a/f out)
    ln_tile_kernel<<<dim3(HW_/32, B_), 256, LN_SMEM>>>(x, ln1_g, ln1_b, ln2_g, ln2_b, t, ah, fh);

    cudaEventRecord(evFork, 0);
    cudaStreamWaitEvent(s2, evFork, 0);

    // FF branch (s2): g = gelu(f @ w_ff1 + b_ff1) [fp16]; ff = g @ w_ff2 + b_ff2 [fp32]
    hgemm_kernel<<<dim3(HID/128, MTOT/128), 256, 0, s2>>>(fh, wff1h, gh,
        MTOT, HID, C_, b_ff1, nullptr, 1, 1);
    hgemm_kernel<<<dim3(C_/128, MTOT/128), 256, 0, s2>>>(gh, wff2h, ff,
        MTOT, C_, HID, b_ff2, nullptr, 0, 0);
    cudaEventRecord(evJoin, s2);

    // Attention branch (s0)
    hgemm_kernel<<<dim3(3*INNER/128, MTOT/128), 256>>>(ah, wqkvh, qkv,
        MTOT, 3*INNER, C_, nullptr, nullptr, 0, 0);
    attn_mma_kernel<<<B_*HEADS, 256, ATT_SMEM_B>>>(qkv, bias_table, oh);
    hgemm_kernel<<<dim3(C_/128, MTOT/128), 256>>>(oh, wouth, s1,
        MTOT, C_, INNER, b_out, t, 0, 0);

    // join, then fused add + transpose
    cudaStreamWaitEvent(0, evJoin, 0);
    transpose_add_kernel<<<dim3(C_/32, HW_/32, B_), dim3(32, 8)>>>(s1, ff, (float*)d_out);
}

// round 10
// speedup vs baseline: 2.2067x; 1.0281x over previous
#include <cuda_runtime.h>
#include <cuda_fp16.h>
#include <math.h>

// ---------------- problem constants ----------------
#define B_   64
#define C_   384
#define HW_  256            // n = H*W
#define MTOT (B_*HW_)       // 16384
#define HEADS 8
#define DHEAD 32
#define INNER (HEADS*DHEAD) // 256
#define HID   (4*C_)        // 1536

// ---------------- device scratch (allocation-free rule) ----------------
__device__ float g_t  [MTOT*C_];
__device__ float g_s1 [MTOT*C_];
__device__ float g_ff [MTOT*C_];
__device__ __align__(16) __half g_qkvh[MTOT*3*INNER];
__device__ __align__(16) __half g_ah [MTOT*C_];
__device__ __align__(16) __half g_fh [MTOT*C_];
__device__ __align__(16) __half g_oh [MTOT*INNER];
__device__ __align__(16) __half g_gh [MTOT*HID];
__device__ __align__(16) __half g_wqkvh[C_*3*INNER];
__device__ __align__(16) __half g_wouth[INNER*C_];
__device__ __align__(16) __half g_wff1h[C_*HID];
__device__ __align__(16) __half g_wff2h[HID*C_];

// ---------------- fp32 -> fp16 converter (weights) ----------------
__global__ void f2h_kernel(const float* __restrict__ src, __half* __restrict__ dst)
{
    int i = (blockIdx.x*256 + threadIdx.x)*4;
    float4 v = *(const float4*)&src[i];
    __half2 h01 = __floats2half2_rn(v.x, v.y);
    __half2 h23 = __floats2half2_rn(v.z, v.w);
    *(uint2*)&dst[i] = make_uint2(*(unsigned*)&h01, *(unsigned*)&h23);
}

// ---------------- tiled transpose + dual LayerNorm (coalesced; fp16 a/f) ----------------
#define LN_SMEM (C_*33*4)
__global__ __launch_bounds__(256)
void ln_tile_kernel(const float* __restrict__ x,
                    const float* __restrict__ g1, const float* __restrict__ b1,
                    const float* __restrict__ g2, const float* __restrict__ b2,
                    float* __restrict__ t, __half* __restrict__ a, __half* __restrict__ f)
{
    extern __shared__ float tile[];   // [C_][33]
    const int tid = threadIdx.x;
    const int p0  = blockIdx.x * 32;
    const int b   = blockIdx.y;

    #pragma unroll
    for (int i = 0; i < 12; i++) {
        int l  = tid + i*256;
        int c  = l >> 3;
        int p4 = (l & 7) * 4;
        float4 v = *(const float4*)&x[((size_t)b*C_ + c)*HW_ + p0 + p4];
        tile[c*33 + p4 + 0] = v.x;
        tile[c*33 + p4 + 1] = v.y;
        tile[c*33 + p4 + 2] = v.z;
        tile[c*33 + p4 + 3] = v.w;
    }
    __syncthreads();

    const int jj = tid & 7;
    const int pp = tid >> 3;

    float vals[48];
    #pragma unroll
    for (int i = 0; i < 12; i++) {
        int c4 = (jj + 8*i) * 4;
        #pragma unroll
        for (int k = 0; k < 4; k++)
            vals[i*4 + k] = tile[(c4 + k)*33 + pp];
    }

    float s = 0.f;
    #pragma unroll
    for (int v = 0; v < 48; v++) s += vals[v];
    #pragma unroll
    for (int o = 4; o; o >>= 1) s += __shfl_down_sync(0xffffffffu, s, o, 8);
    float mean = __shfl_sync(0xffffffffu, s, 0, 8) * (1.f/384.f);

    float sq = 0.f;
    #pragma unroll
    for (int v = 0; v < 48; v++) { float d = vals[v] - mean; sq += d*d; }
    #pragma unroll
    for (int o = 4; o; o >>= 1) sq += __shfl_down_sync(0xffffffffu, sq, o, 8);
    float rstd = rsqrtf(__shfl_sync(0xffffffffu, sq, 0, 8) * (1.f/384.f) + 1e-5f);

    const size_t base = (size_t)(b*HW_ + p0 + pp) * C_;
    #pragma unroll
    for (int i = 0; i < 12; i++) {
        int c4 = (jj + 8*i) * 4;
        float4 tv = make_float4(vals[i*4+0], vals[i*4+1], vals[i*4+2], vals[i*4+3]);
        *(float4*)&t[base + c4] = tv;
        float4 G1 = *(const float4*)&g1[c4];
        float4 B1 = *(const float4*)&b1[c4];
        float4 G2 = *(const float4*)&g2[c4];
        float4 B2 = *(const float4*)&b2[c4];
        float n0 = (tv.x - mean)*rstd, n1 = (tv.y - mean)*rstd;
        float n2 = (tv.z - mean)*rstd, n3 = (tv.w - mean)*rstd;
        __half2 a01 = __floats2half2_rn(n0*G1.x+B1.x, n1*G1.y+B1.y);
        __half2 a23 = __floats2half2_rn(n2*G1.z+B1.z, n3*G1.w+B1.w);
        __half2 f01 = __floats2half2_rn(n0*G2.x+B2.x, n1*G2.y+B2.y);
        __half2 f23 = __floats2half2_rn(n2*G2.z+B2.z, n3*G2.w+B2.w);
        *(uint2*)&a[base + c4] = make_uint2(*(unsigned*)&a01, *(unsigned*)&a23);
        *(uint2*)&f[base + c4] = make_uint2(*(unsigned*)&f01, *(unsigned*)&f23);
    }
}

// ---------------- fp16 tensor-core GEMM (R9, unchanged) ----------------
__global__ __launch_bounds__(256, 2)
void hgemm_kernel(const __half* __restrict__ A, const __half* __restrict__ Bm,
                  void* __restrict__ Cout, int M, int N, int K,
                  const float* __restrict__ bias, const float* __restrict__ add,
                  int do_gelu, int out_half)
{
    __shared__ __half As[2][128][40];
    __shared__ __half Bs[2][32][136];

    const int tid  = threadIdx.x;
    const int warp = tid >> 5;
    const int lane = tid & 31;
    const int g    = lane >> 2;
    const int t4   = lane & 3;

    const int brow = blockIdx.y * 128;
    const int bcol = blockIdx.x * 128;

    const int wr = warp & 3;
    const int wc = warp >> 2;

    float acc[2][8][4];
    #pragma unroll
    for (int mi = 0; mi < 2; mi++)
        #pragma unroll
        for (int ni = 0; ni < 8; ni++)
            #pragma unroll
            for (int e = 0; e < 4; e++) acc[mi][ni][e] = 0.f;

    const int a_row = tid >> 1;
    const int a_k16 = (tid & 1) * 16;
    const int b_row = tid >> 3;
    const int b_c16 = (tid & 7) * 16;

    auto issue = [&](int kt, int buf) {
        int k0 = kt * 32;
        {
            const __half* src = &A[(size_t)(brow + a_row)*K + k0 + a_k16];
            unsigned dst = (unsigned)__cvta_generic_to_shared(&As[buf][a_row][a_k16]);
            asm volatile("cp.async.cg.shared.global [%0], [%1], 16;" :: "r"(dst), "l"(src));
            asm volatile("cp.async.cg.shared.global [%0], [%1], 16;" :: "r"(dst+16), "l"(src+8));
        }
        {
            const __half* src = &Bm[(size_t)(k0 + b_row)*N + bcol + b_c16];
            unsigned dst = (unsigned)__cvta_generic_to_shared(&Bs[buf][b_row][b_c16]);
            asm volatile("cp.async.cg.shared.global [%0], [%1], 16;" :: "r"(dst), "l"(src));
            asm volatile("cp.async.cg.shared.global [%0], [%1], 16;" :: "r"(dst+16), "l"(src+8));
        }
        asm volatile("cp.async.commit_group;");
    };

    const int lm_r   = lane & 7;
    const int lm_m01 = (lane >> 3) & 1;
    const int lm_m23 = lane >> 4;

    auto compute = [&](int buf) {
        #pragma unroll
        for (int sub = 0; sub < 2; sub++) {
            const int koff = sub * 16;
            unsigned a[2][4];
            #pragma unroll
            for (int mi = 0; mi < 2; mi++) {
                unsigned addr = (unsigned)__cvta_generic_to_shared(
                    &As[buf][wr*32 + mi*16 + lm_m01*8 + lm_r][koff + lm_m23*8]);
                asm volatile("ldmatrix.sync.aligned.m8n8.x4.shared.b16 {%0,%1,%2,%3}, [%4];"
                    : "=r"(a[mi][0]), "=r"(a[mi][1]), "=r"(a[mi][2]), "=r"(a[mi][3])
                    : "r"(addr));
            }
            unsigned bfr[8][2];
            #pragma unroll
            for (int p = 0; p < 4; p++) {
                unsigned addr = (unsigned)__cvta_generic_to_shared(
                    &Bs[buf][koff + lm_m01*8 + lm_r][wc*64 + p*16 + lm_m23*8]);
                unsigned r0, r1, r2, r3;
                asm volatile("ldmatrix.sync.aligned.m8n8.x4.trans.shared.b16 {%0,%1,%2,%3}, [%4];"
                    : "=r"(r0), "=r"(r1), "=r"(r2), "=r"(r3)
                    : "r"(addr));
                bfr[2*p][0] = r0;  bfr[2*p][1] = r1;
                bfr[2*p+1][0] = r2; bfr[2*p+1][1] = r3;
            }
            #pragma unroll
            for (int ni = 0; ni < 8; ni++)
                #pragma unroll
                for (int mi = 0; mi < 2; mi++) {
                    asm volatile(
                        "mma.sync.aligned.m16n8k16.row.col.f32.f16.f16.f32 "
                        "{%0,%1,%2,%3},{%4,%5,%6,%7},{%8,%9},{%0,%1,%2,%3};"
                        : "+f"(acc[mi][ni][0]), "+f"(acc[mi][ni][1]),
                          "+f"(acc[mi][ni][2]), "+f"(acc[mi][ni][3])
                        : "r"(a[mi][0]), "r"(a[mi][1]), "r"(a[mi][2]), "r"(a[mi][3]),
                          "r"(bfr[ni][0]), "r"(bfr[ni][1]));
                }
        }
    };

    const int nkt = K >> 5;
    issue(0, 0);
    for (int kt = 0; kt < nkt; kt++) {
        if (kt + 1 < nkt) {
            issue(kt + 1, (kt + 1) & 1);
            asm volatile("cp.async.wait_group 1;");
        } else {
            asm volatile("cp.async.wait_group 0;");
        }
        __syncthreads();
        compute(kt & 1);
        __syncthreads();
    }

    #pragma unroll
    for (int mi = 0; mi < 2; mi++) {
        int r0 = brow + wr*32 + mi*16 + g;
        #pragma unroll
        for (int ni = 0; ni < 8; ni++) {
            int col = bcol + wc*64 + ni*8 + 2*t4;
            float v0 = acc[mi][ni][0];
            float v1 = acc[mi][ni][1];
            float v2 = acc[mi][ni][2];
            float v3 = acc[mi][ni][3];
            if (bias) {
                float bz0 = bias[col], bz1 = bias[col+1];
                v0 += bz0; v1 += bz1; v2 += bz0; v3 += bz1;
            }
            if (do_gelu) {
                v0 = 0.5f*v0*(1.f + erff(v0*0.70710678118654752f));
                v1 = 0.5f*v1*(1.f + erff(v1*0.70710678118654752f));
                v2 = 0.5f*v2*(1.f + erff(v2*0.70710678118654752f));
                v3 = 0.5f*v3*(1.f + erff(v3*0.70710678118654752f));
            }
            if (add) {
                float2 a0 = *(const float2*)&add[(size_t)r0*N + col];
                float2 a1 = *(const float2*)&add[(size_t)(r0+8)*N + col];
                v0 += a0.x; v1 += a0.y; v2 += a1.x; v3 += a1.y;
            }
            if (out_half) {
                __half* Ch = (__half*)Cout;
                __half2 h01 = __floats2half2_rn(v0, v1);
                __half2 h23 = __floats2half2_rn(v2, v3);
                *(unsigned*)&Ch[(size_t)r0*N + col]     = *(unsigned*)&h01;
                *(unsigned*)&Ch[(size_t)(r0+8)*N + col] = *(unsigned*)&h23;
            } else {
                float* C = (float*)Cout;
                *(float2*)&C[(size_t)r0*N + col]     = make_float2(v0, v1);
                *(float2*)&C[(size_t)(r0+8)*N + col] = make_float2(v2, v3);
            }
        }
    }
}

// ---------------- tensor-core attention, full fp16 operand path ----------------
// qkv is fp16. S = Q K^T via m16n8k16 fp16 (K staged [j][d] pitch 40 halves,
// conflict-free), P = exp(S+bias) packed to fp16, O += P V (V^T staged fp16).
#define ATT_KS_H  (256*40)     // K tile halves
#define ATT_VS_H  (32*264)     // V^T tile halves
#define ATT_SMEM_B (ATT_KS_H*2 + ATT_VS_H*2 + 961*4)   // 41220 B

__global__ void attn_mma_kernel(const __half* __restrict__ qkv,
                                const float* __restrict__ bias_table,
                                __half* __restrict__ o)
{
    extern __shared__ char smc[];
    __half* ks  = (__half*)smc;                 // [256][40]
    __half* vs  = ks + ATT_KS_H;                // [32][264]
    float*  bsh = (float*)(vs + ATT_VS_H);      // [961]

    const int b = blockIdx.x >> 3, h = blockIdx.x & 7;
    const int tid = threadIdx.x, warp = tid >> 5, lane = tid & 31;
    const int g = lane >> 2, t4 = lane & 3;
    const __half* base = qkv + (size_t)b * HW_ * 768;

    // stage K [j][d] and V^T [d][j]
    for (int l = tid; l < 2048; l += 256) {
        int j = l >> 3, c4 = (l & 7) * 4;
        uint2 kv = *(const uint2*)&base[(size_t)j*768 + 256 + h*32 + c4];
        *(uint2*)&ks[j*40 + c4] = kv;
        __half vh[4];
        *(uint2*)vh = *(const uint2*)&base[(size_t)j*768 + 512 + h*32 + c4];
        vs[(c4+0)*264 + j] = vh[0];
        vs[(c4+1)*264 + j] = vh[1];
        vs[(c4+2)*264 + j] = vh[2];
        vs[(c4+3)*264 + j] = vh[3];
    }
    for (int l = tid; l < 961; l += 256) bsh[l] = bias_table[(size_t)l*8 + h];

    // Q fragments (fp16, scaled), m16n8k16 A layout: [mi][kstep][4]
    const float scale = 0.17677669529663688f;
    unsigned qa[2][2][4];
    #pragma unroll
    for (int mi = 0; mi < 2; mi++) {
        int r0 = warp*32 + mi*16 + g;
        const __half* q0 = &base[(size_t)r0*768 + h*32];
        const __half* q1 = &base[(size_t)(r0+8)*768 + h*32];
        #pragma unroll
        for (int s = 0; s < 2; s++) {
            #pragma unroll
            for (int e = 0; e < 4; e++) {
                const __half* src = (e & 1) ? q1 : q0;
                int k = s*16 + 2*t4 + ((e >> 1) ? 8 : 0);
                float2 qq = __half22float2(*(const __half2*)&src[k]);
                __half2 hh = __floats2half2_rn(qq.x*scale, qq.y*scale);
                qa[mi][s][e] = *(unsigned*)&hh;
            }
        }
    }

    int bb[2][2];
    #pragma unroll
    for (int mi = 0; mi < 2; mi++) {
        int i0 = warp*32 + mi*16 + g;
        bb[mi][0] = ((i0 >> 4) + 15)*31 + (i0 & 15) + 15;
        bb[mi][1] = (((i0+8) >> 4) + 15)*31 + ((i0+8) & 15) + 15;
    }
    __syncthreads();

    float acco[2][4][4];
    #pragma unroll
    for (int mi = 0; mi < 2; mi++)
        #pragma unroll
        for (int vn = 0; vn < 4; vn++)
            #pragma unroll
            for (int e = 0; e < 4; e++) acco[mi][vn][e] = 0.f;
    float rs[2][2] = {{0.f, 0.f}, {0.f, 0.f}};

    for (int j0 = 0; j0 < 256; j0 += 32) {
        // ---- S = Q K^T chunk (fp16 mma) ----
        float accs[2][4][4];
        #pragma unroll
        for (int mi = 0; mi < 2; mi++)
            #pragma unroll
            for (int ni = 0; ni < 4; ni++)
                #pragma unroll
                for (int e = 0; e < 4; e++) accs[mi][ni][e] = 0.f;

        #pragma unroll
        for (int s = 0; s < 2; s++) {
            #pragma unroll
            for (int ni = 0; ni < 4; ni++) {
                const __half* kr = &ks[(j0 + ni*8 + g)*40 + s*16 + 2*t4];
                unsigned kb0 = *(const unsigned*)&kr[0];
                unsigned kb1 = *(const unsigned*)&kr[8];
                #pragma unroll
                for (int mi = 0; mi < 2; mi++) {
                    asm volatile(
                        "mma.sync.aligned.m16n8k16.row.col.f32.f16.f16.f32 "
                        "{%0,%1,%2,%3},{%4,%5,%6,%7},{%8,%9},{%0,%1,%2,%3};"
                        : "+f"(accs[mi][ni][0]), "+f"(accs[mi][ni][1]),
                          "+f"(accs[mi][ni][2]), "+f"(accs[mi][ni][3])
                        : "r"(qa[mi][s][0]), "r"(qa[mi][s][1]),
                          "r"(qa[mi][s][2]), "r"(qa[mi][s][3]),
                          "r"(kb0), "r"(kb1));
                }
            }
        }

        // ---- P = exp(S + bias), rowsum, pack ----
        unsigned pk[2][4][2];
        #pragma unroll
        for (int mi = 0; mi < 2; mi++) {
            #pragma unroll
            for (int ni = 0; ni < 4; ni++) {
                int j  = j0 + ni*8 + 2*t4;
                int o0 = (j >> 4)*31 + (j & 15);
                int o1 = ((j+1) >> 4)*31 + ((j+1) & 15);
                float p0 = __expf(accs[mi][ni][0] + bsh[bb[mi][0] - o0]);
                float p1 = __expf(accs[mi][ni][1] + bsh[bb[mi][0] - o1]);
                float p2 = __expf(accs[mi][ni][2] + bsh[bb[mi][1] - o0]);
                float p3 = __expf(accs[mi][ni][3] + bsh[bb[mi][1] - o1]);
                rs[mi][0] += p0 + p1;
                rs[mi][1] += p2 + p3;
                __half2 h01 = __floats2half2_rn(p0, p1);
                __half2 h23 = __floats2half2_rn(p2, p3);
                pk[mi][ni][0] = *(unsigned*)&h01;
                pk[mi][ni][1] = *(unsigned*)&h23;
            }
        }

        // ---- O += P V ----
        #pragma unroll
        for (int k = 0; k < 2; k++) {
            #pragma unroll
            for (int vn = 0; vn < 4; vn++) {
                unsigned vb0 = *(const unsigned*)&vs[(vn*8 + g)*264 + j0 + k*16 + 2*t4];
                unsigned vb1 = *(const unsigned*)&vs[(vn*8 + g)*264 + j0 + k*16 + 2*t4 + 8];
                #pragma unroll
                for (int mi = 0; mi < 2; mi++) {
                    asm volatile(
                        "mma.sync.aligned.m16n8k16.row.col.f32.f16.f16.f32 "
                        "{%0,%1,%2,%3},{%4,%5,%6,%7},{%8,%9},{%0,%1,%2,%3};"
                        : "+f"(acco[mi][vn][0]), "+f"(acco[mi][vn][1]),
                          "+f"(acco[mi][vn][2]), "+f"(acco[mi][vn][3])
                        : "r"(pk[mi][2*k][0]), "r"(pk[mi][2*k][1]),
                          "r"(pk[mi][2*k+1][0]), "r"(pk[mi][2*k+1][1]),
                          "r"(vb0), "r"(vb1));
                }
            }
        }
    }

    #pragma unroll
    for (int mi = 0; mi < 2; mi++)
        #pragma unroll
        for (int r = 0; r < 2; r++) {
            float v = rs[mi][r];
            v += __shfl_xor_sync(0xffffffffu, v, 1);
            v += __shfl_xor_sync(0xffffffffu, v, 2);
            rs[mi][r] = 1.f / v;
        }

    #pragma unroll
    for (int mi = 0; mi < 2; mi++) {
        int r0 = warp*32 + mi*16 + g;
        #pragma unroll
        for (int vn = 0; vn < 4; vn++) {
            int col = h*32 + vn*8 + 2*t4;
            __half2 h0 = __floats2half2_rn(acco[mi][vn][0]*rs[mi][0], acco[mi][vn][1]*rs[mi][0]);
            __half2 h1 = __floats2half2_rn(acco[mi][vn][2]*rs[mi][1], acco[mi][vn][3]*rs[mi][1]);
            *(unsigned*)&o[((size_t)(b*HW_) + r0)*INNER + col]     = *(unsigned*)&h0;
            *(unsigned*)&o[((size_t)(b*HW_) + r0 + 8)*INNER + col] = *(unsigned*)&h1;
        }
    }
}

// ---------------- fused join: out[B,C,H,W] = transpose(s1 + ff) ----------------
__global__ void transpose_add_kernel(const float* __restrict__ s1,
                                     const float* __restrict__ ff,
                                     float* __restrict__ out)
{
    __shared__ float tile[32][33];
    int b  = blockIdx.z;
    int c0 = blockIdx.x * 32;
    int p0 = blockIdx.y * 32;

    for (int i = threadIdx.y; i < 32; i += 8) {
        size_t idx = (size_t)(b*HW_ + p0 + i)*C_ + c0 + threadIdx.x;
        tile[i][threadIdx.x] = s1[idx] + ff[idx];
    }
    __syncthreads();
    float* ob = out + (size_t)b * C_ * HW_;
    for (int i = threadIdx.y; i < 32; i += 8)
        ob[(size_t)(c0 + i)*HW_ + p0 + threadIdx.x] = tile[threadIdx.x][i];
}

// ---------------- launch ----------------
extern "C" void kernel_launch(void* const* d_in, const int* in_sizes, int n_in,
                              void* d_out, int out_size)
{
    const float* x          = (const float*)d_in[0];
    const float* ln1_g      = (const float*)d_in[1];
    const float* ln1_b      = (const float*)d_in[2];
    const float* w_qkv      = (const float*)d_in[3];
    const float* bias_table = (const float*)d_in[4];
    const float* w_out      = (const float*)d_in[5];
    const float* b_out      = (const float*)d_in[6];
    const float* ln2_g      = (const float*)d_in[7];
    const float* ln2_b      = (const float*)d_in[8];
    const float* w_ff1      = (const float*)d_in[9];
    const float* b_ff1      = (const float*)d_in[10];
    const float* w_ff2      = (const float*)d_in[11];
    const float* b_ff2      = (const float*)d_in[12];

    float *t, *s1, *ff;
    __half *qkvh, *ah, *fh, *oh, *gh, *wqkvh, *wouth, *wff1h, *wff2h;
    cudaGetSymbolAddress((void**)&t,     g_t);
    cudaGetSymbolAddress((void**)&s1,    g_s1);
    cudaGetSymbolAddress((void**)&ff,    g_ff);
    cudaGetSymbolAddress((void**)&qkvh,  g_qkvh);
    cudaGetSymbolAddress((void**)&ah,    g_ah);
    cudaGetSymbolAddress((void**)&fh,    g_fh);
    cudaGetSymbolAddress((void**)&oh,    g_oh);
    cudaGetSymbolAddress((void**)&gh,    g_gh);
    cudaGetSymbolAddress((void**)&wqkvh, g_wqkvh);
    cudaGetSymbolAddress((void**)&wouth, g_wouth);
    cudaGetSymbolAddress((void**)&wff1h, g_wff1h);
    cudaGetSymbolAddress((void**)&wff2h, g_wff2h);

    cudaFuncSetAttribute(attn_mma_kernel, cudaFuncAttributeMaxDynamicSharedMemorySize, ATT_SMEM_B);
    cudaFuncSetAttribute(ln_tile_kernel,  cudaFuncAttributeMaxDynamicSharedMemorySize, LN_SMEM);

    static cudaStream_t s2 = nullptr;
    static cudaEvent_t ev0 = nullptr, evFork = nullptr, evJoin = nullptr;
    if (!s2) {
        cudaStreamCreateWithFlags(&s2, cudaStreamNonBlocking);
        cudaEventCreateWithFlags(&ev0,    cudaEventDisableTiming);
        cudaEventCreateWithFlags(&evFork, cudaEventDisableTiming);
        cudaEventCreateWithFlags(&evJoin, cudaEventDisableTiming);
    }

    // weight converts: FF weights on s2, attention weights on s0
    cudaEventRecord(ev0, 0);
    cudaStreamWaitEvent(s2, ev0, 0);
    f2h_kernel<<<(C_*HID)/1024,  256, 0, s2>>>(w_ff1, wff1h);
    f2h_kernel<<<(HID*C_)/1024,  256, 0, s2>>>(w_ff2, wff2h);

    f2h_kernel<<<(C_*3*INNER)/1024, 256>>>(w_qkv, wqkvh);
    f2h_kernel<<<(INNER*C_)/1024,   256>>>(w_out, wouth);

    // transpose + LN1 + LN2 (fp16 a/f)
    ln_tile_kernel<<<dim3(HW_/32, B_), 256, LN_SMEM>>>(x, ln1_g, ln1_b, ln2_g, ln2_b, t, ah, fh);

    cudaEventRecord(evFork, 0);
    cudaStreamWaitEvent(s2, evFork, 0);

    // FF branch (s2)
    hgemm_kernel<<<dim3(HID/128, MTOT/128), 256, 0, s2>>>(fh, wff1h, gh,
        MTOT, HID, C_, b_ff1, nullptr, 1, 1);
    hgemm_kernel<<<dim3(C_/128, MTOT/128), 256, 0, s2>>>(gh, wff2h, ff,
        MTOT, C_, HID, b_ff2, nullptr, 0, 0);
    cudaEventRecord(evJoin, s2);

    // Attention branch (s0): qkv now fp16
    hgemm_kernel<<<dim3(3*INNER/128, MTOT/128), 256>>>(ah, wqkvh, qkvh,
        MTOT, 3*INNER, C_, nullptr, nullptr, 0, 1);
    attn_mma_kernel<<<B_*HEADS, 256, ATT_SMEM_B>>>(qkvh, bias_table, oh);
    hgemm_kernel<<<dim3(C_/128, MTOT/128), 256>>>(oh, wouth, s1,
        MTOT, C_, INNER, b_out, t, 0, 0);

    // join + fused add-transpose
    cudaStreamWaitEvent(0, evJoin, 0);
    transpose_add_kernel<<<dim3(C_/32, HW_/32, B_), dim3(32, 8)>>>(s1, ff, (float*)d_out);
}

// round 11
// speedup vs baseline: 2.3754x; 1.0764x over previous
#include <cuda_runtime.h>
#include <cuda_fp16.h>
#include <math.h>

// ---------------- problem constants ----------------
#define B_   64
#define C_   384
#define HW_  256            // n = H*W
#define MTOT (B_*HW_)       // 16384
#define HEADS 8
#define DHEAD 32
#define INNER (HEADS*DHEAD) // 256
#define HID   (4*C_)        // 1536

// ---------------- device scratch (allocation-free rule) ----------------
__device__ float g_t  [MTOT*C_];
__device__ float g_s1 [MTOT*C_];
__device__ float g_ff [MTOT*C_];
__device__ __align__(16) __half g_qkvh[MTOT*3*INNER];
__device__ __align__(16) __half g_ah [MTOT*C_];
__device__ __align__(16) __half g_fh [MTOT*C_];
__device__ __align__(16) __half g_oh [MTOT*INNER];
__device__ __align__(16) __half g_gh [MTOT*HID];
__device__ __align__(16) __half g_wqkvh[C_*3*INNER];
__device__ __align__(16) __half g_wouth[INNER*C_];
__device__ __align__(16) __half g_wff1h[C_*HID];
__device__ __align__(16) __half g_wff2h[HID*C_];

// ---------------- fp32 -> fp16 converter (two arrays per launch) ----------------
__global__ void f2h2_kernel(const float* __restrict__ sA, __half* __restrict__ dA, int nA,
                            const float* __restrict__ sB, __half* __restrict__ dB)
{
    int i = (blockIdx.x*256 + threadIdx.x)*4;
    const float* s; __half* d; int j;
    if (i < nA) { s = sA; d = dA; j = i; }
    else        { s = sB; d = dB; j = i - nA; }
    float4 v = *(const float4*)&s[j];
    __half2 h01 = __floats2half2_rn(v.x, v.y);
    __half2 h23 = __floats2half2_rn(v.z, v.w);
    *(uint2*)&d[j] = make_uint2(*(unsigned*)&h01, *(unsigned*)&h23);
}

// ---------------- tiled transpose + dual LayerNorm (coalesced; fp16 a/f) ----------------
#define LN_SMEM (C_*33*4)
__global__ __launch_bounds__(256)
void ln_tile_kernel(const float* __restrict__ x,
                    const float* __restrict__ g1, const float* __restrict__ b1,
                    const float* __restrict__ g2, const float* __restrict__ b2,
                    float* __restrict__ t, __half* __restrict__ a, __half* __restrict__ f)
{
    extern __shared__ float tile[];   // [C_][33]
    const int tid = threadIdx.x;
    const int p0  = blockIdx.x * 32;
    const int b   = blockIdx.y;

    #pragma unroll
    for (int i = 0; i < 12; i++) {
        int l  = tid + i*256;
        int c  = l >> 3;
        int p4 = (l & 7) * 4;
        float4 v = *(const float4*)&x[((size_t)b*C_ + c)*HW_ + p0 + p4];
        tile[c*33 + p4 + 0] = v.x;
        tile[c*33 + p4 + 1] = v.y;
        tile[c*33 + p4 + 2] = v.z;
        tile[c*33 + p4 + 3] = v.w;
    }
    __syncthreads();

    const int jj = tid & 7;
    const int pp = tid >> 3;

    float vals[48];
    #pragma unroll
    for (int i = 0; i < 12; i++) {
        int c4 = (jj + 8*i) * 4;
        #pragma unroll
        for (int k = 0; k < 4; k++)
            vals[i*4 + k] = tile[(c4 + k)*33 + pp];
    }

    float s = 0.f;
    #pragma unroll
    for (int v = 0; v < 48; v++) s += vals[v];
    #pragma unroll
    for (int o = 4; o; o >>= 1) s += __shfl_down_sync(0xffffffffu, s, o, 8);
    float mean = __shfl_sync(0xffffffffu, s, 0, 8) * (1.f/384.f);

    float sq = 0.f;
    #pragma unroll
    for (int v = 0; v < 48; v++) { float d = vals[v] - mean; sq += d*d; }
    #pragma unroll
    for (int o = 4; o; o >>= 1) sq += __shfl_down_sync(0xffffffffu, sq, o, 8);
    float rstd = rsqrtf(__shfl_sync(0xffffffffu, sq, 0, 8) * (1.f/384.f) + 1e-5f);

    const size_t base = (size_t)(b*HW_ + p0 + pp) * C_;
    #pragma unroll
    for (int i = 0; i < 12; i++) {
        int c4 = (jj + 8*i) * 4;
        float4 tv = make_float4(vals[i*4+0], vals[i*4+1], vals[i*4+2], vals[i*4+3]);
        *(float4*)&t[base + c4] = tv;
        float4 G1 = *(const float4*)&g1[c4];
        float4 B1 = *(const float4*)&b1[c4];
        float4 G2 = *(const float4*)&g2[c4];
        float4 B2 = *(const float4*)&b2[c4];
        float n0 = (tv.x - mean)*rstd, n1 = (tv.y - mean)*rstd;
        float n2 = (tv.z - mean)*rstd, n3 = (tv.w - mean)*rstd;
        __half2 a01 = __floats2half2_rn(n0*G1.x+B1.x, n1*G1.y+B1.y);
        __half2 a23 = __floats2half2_rn(n2*G1.z+B1.z, n3*G1.w+B1.w);
        __half2 f01 = __floats2half2_rn(n0*G2.x+B2.x, n1*G2.y+B2.y);
        __half2 f23 = __floats2half2_rn(n2*G2.z+B2.z, n3*G2.w+B2.w);
        *(uint2*)&a[base + c4] = make_uint2(*(unsigned*)&a01, *(unsigned*)&a23);
        *(uint2*)&f[base + c4] = make_uint2(*(unsigned*)&f01, *(unsigned*)&f23);
    }
}

// ---------------- fp16 tensor-core GEMM, 3-stage single-sync pipeline ----------------
// BM=128 BN=128 BK=32, 256 threads (8 warps 4x2), warp tile 32x64 (m16n8k16).
// Stage layout in dynamic smem (halves): As[s]=128x40 at s*AS_STAGE,
// Bs[s]=32x136 at 3*AS_STAGE + s*BS_STAGE. Stage indices are compile-time
// literals (loop unrolled by 3) so all LDS/ldmatrix addresses fold.
#define AS_STAGE (128*40)
#define BS_STAGE (32*136)
#define HG_SMEM  ((3*AS_STAGE + 3*BS_STAGE)*2)   // 56832 bytes

__global__ __launch_bounds__(256, 2)
void hgemm_kernel(const __half* __restrict__ A, const __half* __restrict__ Bm,
                  void* __restrict__ Cout, int M, int N, int K,
                  const float* __restrict__ bias, const float* __restrict__ add,
                  int do_gelu, int out_half)
{
    extern __shared__ __half hsm[];

    const int tid  = threadIdx.x;
    const int warp = tid >> 5;
    const int lane = tid & 31;
    const int g    = lane >> 2;
    const int t4   = lane & 3;

    const int brow = blockIdx.y * 128;
    const int bcol = blockIdx.x * 128;

    const int wr = warp & 3;
    const int wc = warp >> 2;

    float acc[2][8][4];
    #pragma unroll
    for (int mi = 0; mi < 2; mi++)
        #pragma unroll
        for (int ni = 0; ni < 8; ni++)
            #pragma unroll
            for (int e = 0; e < 4; e++) acc[mi][ni][e] = 0.f;

    const int a_row = tid >> 1;
    const int a_k16 = (tid & 1) * 16;
    const int b_row = tid >> 3;
    const int b_c16 = (tid & 7) * 16;

    auto issue = [&](int kt, int buf) {
        int k0 = kt * 32;
        {
            const __half* src = &A[(size_t)(brow + a_row)*K + k0 + a_k16];
            unsigned dst = (unsigned)__cvta_generic_to_shared(
                &hsm[buf*AS_STAGE + a_row*40 + a_k16]);
            asm volatile("cp.async.cg.shared.global [%0], [%1], 16;" :: "r"(dst), "l"(src));
            asm volatile("cp.async.cg.shared.global [%0], [%1], 16;" :: "r"(dst+16), "l"(src+8));
        }
        {
            const __half* src = &Bm[(size_t)(k0 + b_row)*N + bcol + b_c16];
            unsigned dst = (unsigned)__cvta_generic_to_shared(
                &hsm[3*AS_STAGE + buf*BS_STAGE + b_row*136 + b_c16]);
            asm volatile("cp.async.cg.shared.global [%0], [%1], 16;" :: "r"(dst), "l"(src));
            asm volatile("cp.async.cg.shared.global [%0], [%1], 16;" :: "r"(dst+16), "l"(src+8));
        }
        asm volatile("cp.async.commit_group;");
    };

    const int lm_r   = lane & 7;
    const int lm_m01 = (lane >> 3) & 1;
    const int lm_m23 = lane >> 4;

    auto compute = [&](const int buf) {
        const __half* as = &hsm[buf*AS_STAGE];
        const __half* bs = &hsm[3*AS_STAGE + buf*BS_STAGE];
        #pragma unroll
        for (int sub = 0; sub < 2; sub++) {
            const int koff = sub * 16;
            unsigned a[2][4];
            #pragma unroll
            for (int mi = 0; mi < 2; mi++) {
                unsigned addr = (unsigned)__cvta_generic_to_shared(
                    &as[(wr*32 + mi*16 + lm_m01*8 + lm_r)*40 + koff + lm_m23*8]);
                asm volatile("ldmatrix.sync.aligned.m8n8.x4.shared.b16 {%0,%1,%2,%3}, [%4];"
                    : "=r"(a[mi][0]), "=r"(a[mi][1]), "=r"(a[mi][2]), "=r"(a[mi][3])
                    : "r"(addr));
            }
            unsigned bfr[8][2];
            #pragma unroll
            for (int p = 0; p < 4; p++) {
                unsigned addr = (unsigned)__cvta_generic_to_shared(
                    &bs[(koff + lm_m01*8 + lm_r)*136 + wc*64 + p*16 + lm_m23*8]);
                unsigned r0, r1, r2, r3;
                asm volatile("ldmatrix.sync.aligned.m8n8.x4.trans.shared.b16 {%0,%1,%2,%3}, [%4];"
                    : "=r"(r0), "=r"(r1), "=r"(r2), "=r"(r3)
                    : "r"(addr));
                bfr[2*p][0] = r0;  bfr[2*p][1] = r1;
                bfr[2*p+1][0] = r2; bfr[2*p+1][1] = r3;
            }
            #pragma unroll
            for (int ni = 0; ni < 8; ni++)
                #pragma unroll
                for (int mi = 0; mi < 2; mi++) {
                    asm volatile(
                        "mma.sync.aligned.m16n8k16.row.col.f32.f16.f16.f32 "
                        "{%0,%1,%2,%3},{%4,%5,%6,%7},{%8,%9},{%0,%1,%2,%3};"
                        : "+f"(acc[mi][ni][0]), "+f"(acc[mi][ni][1]),
                          "+f"(acc[mi][ni][2]), "+f"(acc[mi][ni][3])
                        : "r"(a[mi][0]), "r"(a[mi][1]), "r"(a[mi][2]), "r"(a[mi][3]),
                          "r"(bfr[ni][0]), "r"(bfr[ni][1]));
                }
        }
    };

    const int nkt = K >> 5;   // 8, 12, or 48 here (all >= 3)

    // prefill 2 stages
    issue(0, 0);
    issue(1, 1);
    asm volatile("cp.async.wait_group 1;");
    __syncthreads();

    // single-sync pipeline, unrolled by 3 so stage indices are literals
    for (int kt0 = 0; kt0 < nkt; kt0 += 3) {
        #pragma unroll
        for (int u = 0; u < 3; u++) {
            const int kt = kt0 + u;
            if (kt >= nkt) break;
            compute(u);                          // stage kt lives in buffer u
            if (kt + 2 < nkt) issue(kt + 2, (u + 2) % 3);
            if (kt + 1 < nkt) {
                if (kt + 2 < nkt) { asm volatile("cp.async.wait_group 1;"); }
                else              { asm volatile("cp.async.wait_group 0;"); }
                __syncthreads();
            }
        }
    }

    // ---- epilogue ----
    #pragma unroll
    for (int mi = 0; mi < 2; mi++) {
        int r0 = brow + wr*32 + mi*16 + g;
        #pragma unroll
        for (int ni = 0; ni < 8; ni++) {
            int col = bcol + wc*64 + ni*8 + 2*t4;
            float v0 = acc[mi][ni][0];
            float v1 = acc[mi][ni][1];
            float v2 = acc[mi][ni][2];
            float v3 = acc[mi][ni][3];
            if (bias) {
                float bz0 = bias[col], bz1 = bias[col+1];
                v0 += bz0; v1 += bz1; v2 += bz0; v3 += bz1;
            }
            if (do_gelu) {
                v0 = 0.5f*v0*(1.f + erff(v0*0.70710678118654752f));
                v1 = 0.5f*v1*(1.f + erff(v1*0.70710678118654752f));
                v2 = 0.5f*v2*(1.f + erff(v2*0.70710678118654752f));
                v3 = 0.5f*v3*(1.f + erff(v3*0.70710678118654752f));
            }
            if (add) {
                float2 a0 = *(const float2*)&add[(size_t)r0*N + col];
                float2 a1 = *(const float2*)&add[(size_t)(r0+8)*N + col];
                v0 += a0.x; v1 += a0.y; v2 += a1.x; v3 += a1.y;
            }
            if (out_half) {
                __half* Ch = (__half*)Cout;
                __half2 h01 = __floats2half2_rn(v0, v1);
                __half2 h23 = __floats2half2_rn(v2, v3);
                *(unsigned*)&Ch[(size_t)r0*N + col]     = *(unsigned*)&h01;
                *(unsigned*)&Ch[(size_t)(r0+8)*N + col] = *(unsigned*)&h23;
            } else {
                float* C = (float*)Cout;
                *(float2*)&C[(size_t)r0*N + col]     = make_float2(v0, v1);
                *(float2*)&C[(size_t)(r0+8)*N + col] = make_float2(v2, v3);
            }
        }
    }
}

// ---------------- tensor-core attention, full fp16 operand path (R10) ----------------
#define ATT_KS_H  (256*40)
#define ATT_VS_H  (32*264)
#define ATT_SMEM_B (ATT_KS_H*2 + ATT_VS_H*2 + 961*4)

__global__ void attn_mma_kernel(const __half* __restrict__ qkv,
                                const float* __restrict__ bias_table,
                                __half* __restrict__ o)
{
    extern __shared__ char smc[];
    __half* ks  = (__half*)smc;
    __half* vs  = ks + ATT_KS_H;
    float*  bsh = (float*)(vs + ATT_VS_H);

    const int b = blockIdx.x >> 3, h = blockIdx.x & 7;
    const int tid = threadIdx.x, warp = tid >> 5, lane = tid & 31;
    const int g = lane >> 2, t4 = lane & 3;
    const __half* base = qkv + (size_t)b * HW_ * 768;

    for (int l = tid; l < 2048; l += 256) {
        int j = l >> 3, c4 = (l & 7) * 4;
        uint2 kv = *(const uint2*)&base[(size_t)j*768 + 256 + h*32 + c4];
        *(uint2*)&ks[j*40 + c4] = kv;
        __half vh[4];
        *(uint2*)vh = *(const uint2*)&base[(size_t)j*768 + 512 + h*32 + c4];
        vs[(c4+0)*264 + j] = vh[0];
        vs[(c4+1)*264 + j] = vh[1];
        vs[(c4+2)*264 + j] = vh[2];
        vs[(c4+3)*264 + j] = vh[3];
    }
    for (int l = tid; l < 961; l += 256) bsh[l] = bias_table[(size_t)l*8 + h];

    const float scale = 0.17677669529663688f;
    unsigned qa[2][2][4];
    #pragma unroll
    for (int mi = 0; mi < 2; mi++) {
        int r0 = warp*32 + mi*16 + g;
        const __half* q0 = &base[(size_t)r0*768 + h*32];
        const __half* q1 = &base[(size_t)(r0+8)*768 + h*32];
        #pragma unroll
        for (int s = 0; s < 2; s++) {
            #pragma unroll
            for (int e = 0; e < 4; e++) {
                const __half* src = (e & 1) ? q1 : q0;
                int k = s*16 + 2*t4 + ((e >> 1) ? 8 : 0);
                float2 qq = __half22float2(*(const __half2*)&src[k]);
                __half2 hh = __floats2half2_rn(qq.x*scale, qq.y*scale);
                qa[mi][s][e] = *(unsigned*)&hh;
            }
        }
    }

    int bb[2][2];
    #pragma unroll
    for (int mi = 0; mi < 2; mi++) {
        int i0 = warp*32 + mi*16 + g;
        bb[mi][0] = ((i0 >> 4) + 15)*31 + (i0 & 15) + 15;
        bb[mi][1] = (((i0+8) >> 4) + 15)*31 + ((i0+8) & 15) + 15;
    }
    __syncthreads();

    float acco[2][4][4];
    #pragma unroll
    for (int mi = 0; mi < 2; mi++)
        #pragma unroll
        for (int vn = 0; vn < 4; vn++)
            #pragma unroll
            for (int e = 0; e < 4; e++) acco[mi][vn][e] = 0.f;
    float rs[2][2] = {{0.f, 0.f}, {0.f, 0.f}};

    for (int j0 = 0; j0 < 256; j0 += 32) {
        float accs[2][4][4];
        #pragma unroll
        for (int mi = 0; mi < 2; mi++)
            #pragma unroll
            for (int ni = 0; ni < 4; ni++)
                #pragma unroll
                for (int e = 0; e < 4; e++) accs[mi][ni][e] = 0.f;

        #pragma unroll
        for (int s = 0; s < 2; s++) {
            #pragma unroll
            for (int ni = 0; ni < 4; ni++) {
                const __half* kr = &ks[(j0 + ni*8 + g)*40 + s*16 + 2*t4];
                unsigned kb0 = *(const unsigned*)&kr[0];
                unsigned kb1 = *(const unsigned*)&kr[8];
                #pragma unroll
                for (int mi = 0; mi < 2; mi++) {
                    asm volatile(
                        "mma.sync.aligned.m16n8k16.row.col.f32.f16.f16.f32 "
                        "{%0,%1,%2,%3},{%4,%5,%6,%7},{%8,%9},{%0,%1,%2,%3};"
                        : "+f"(accs[mi][ni][0]), "+f"(accs[mi][ni][1]),
                          "+f"(accs[mi][ni][2]), "+f"(accs[mi][ni][3])
                        : "r"(qa[mi][s][0]), "r"(qa[mi][s][1]),
                          "r"(qa[mi][s][2]), "r"(qa[mi][s][3]),
                          "r"(kb0), "r"(kb1));
                }
            }
        }

        unsigned pk[2][4][2];
        #pragma unroll
        for (int mi = 0; mi < 2; mi++) {
            #pragma unroll
            for (int ni = 0; ni < 4; ni++) {
                int j  = j0 + ni*8 + 2*t4;
                int o0 = (j >> 4)*31 + (j & 15);
                int o1 = ((j+1) >> 4)*31 + ((j+1) & 15);
                float p0 = __expf(accs[mi][ni][0] + bsh[bb[mi][0] - o0]);
                float p1 = __expf(accs[mi][ni][1] + bsh[bb[mi][0] - o1]);
                float p2 = __expf(accs[mi][ni][2] + bsh[bb[mi][1] - o0]);
                float p3 = __expf(accs[mi][ni][3] + bsh[bb[mi][1] - o1]);
                rs[mi][0] += p0 + p1;
                rs[mi][1] += p2 + p3;
                __half2 h01 = __floats2half2_rn(p0, p1);
                __half2 h23 = __floats2half2_rn(p2, p3);
                pk[mi][ni][0] = *(unsigned*)&h01;
                pk[mi][ni][1] = *(unsigned*)&h23;
            }
        }

        #pragma unroll
        for (int k = 0; k < 2; k++) {
            #pragma unroll
            for (int vn = 0; vn < 4; vn++) {
                unsigned vb0 = *(const unsigned*)&vs[(vn*8 + g)*264 + j0 + k*16 + 2*t4];
                unsigned vb1 = *(const unsigned*)&vs[(vn*8 + g)*264 + j0 + k*16 + 2*t4 + 8];
                #pragma unroll
                for (int mi = 0; mi < 2; mi++) {
                    asm volatile(
                        "mma.sync.aligned.m16n8k16.row.col.f32.f16.f16.f32 "
                        "{%0,%1,%2,%3},{%4,%5,%6,%7},{%8,%9},{%0,%1,%2,%3};"
                        : "+f"(acco[mi][vn][0]), "+f"(acco[mi][vn][1]),
                          "+f"(acco[mi][vn][2]), "+f"(acco[mi][vn][3])
                        : "r"(pk[mi][2*k][0]), "r"(pk[mi][2*k][1]),
                          "r"(pk[mi][2*k+1][0]), "r"(pk[mi][2*k+1][1]),
                          "r"(vb0), "r"(vb1));
                }
            }
        }
    }

    #pragma unroll
    for (int mi = 0; mi < 2; mi++)
        #pragma unroll
        for (int r = 0; r < 2; r++) {
            float v = rs[mi][r];
            v += __shfl_xor_sync(0xffffffffu, v, 1);
            v += __shfl_xor_sync(0xffffffffu, v, 2);
            rs[mi][r] = 1.f / v;
        }

    #pragma unroll
    for (int mi = 0; mi < 2; mi++) {
        int r0 = warp*32 + mi*16 + g;
        #pragma unroll
        for (int vn = 0; vn < 4; vn++) {
            int col = h*32 + vn*8 + 2*t4;
            __half2 h0 = __floats2half2_rn(acco[mi][vn][0]*rs[mi][0], acco[mi][vn][1]*rs[mi][0]);
            __half2 h1 = __floats2half2_rn(acco[mi][vn][2]*rs[mi][1], acco[mi][vn][3]*rs[mi][1]);
            *(unsigned*)&o[((size_t)(b*HW_) + r0)*INNER + col]     = *(unsigned*)&h0;
            *(unsigned*)&o[((size_t)(b*HW_) + r0 + 8)*INNER + col] = *(unsigned*)&h1;
        }
    }
}

// ---------------- fused join: out[B,C,H,W] = transpose(s1 + ff) ----------------
__global__ void transpose_add_kernel(const float* __restrict__ s1,
                                     const float* __restrict__ ff,
                                     float* __restrict__ out)
{
    __shared__ float tile[32][33];
    int b  = blockIdx.z;
    int c0 = blockIdx.x * 32;
    int p0 = blockIdx.y * 32;

    for (int i = threadIdx.y; i < 32; i += 8) {
        size_t idx = (size_t)(b*HW_ + p0 + i)*C_ + c0 + threadIdx.x;
        tile[i][threadIdx.x] = s1[idx] + ff[idx];
    }
    __syncthreads();
    float* ob = out + (size_t)b * C_ * HW_;
    for (int i = threadIdx.y; i < 32; i += 8)
        ob[(size_t)(c0 + i)*HW_ + p0 + threadIdx.x] = tile[threadIdx.x][i];
}

// ---------------- launch ----------------
extern "C" void kernel_launch(void* const* d_in, const int* in_sizes, int n_in,
                              void* d_out, int out_size)
{
    const float* x          = (const float*)d_in[0];
    const float* ln1_g      = (const float*)d_in[1];
    const float* ln1_b      = (const float*)d_in[2];
    const float* w_qkv      = (const float*)d_in[3];
    const float* bias_table = (const float*)d_in[4];
    const float* w_out      = (const float*)d_in[5];
    const float* b_out      = (const float*)d_in[6];
    const float* ln2_g      = (const float*)d_in[7];
    const float* ln2_b      = (const float*)d_in[8];
    const float* w_ff1      = (const float*)d_in[9];
    const float* b_ff1      = (const float*)d_in[10];
    const float* w_ff2      = (const float*)d_in[11];
    const float* b_ff2      = (const float*)d_in[12];

    float *t, *s1, *ff;
    __half *qkvh, *ah, *fh, *oh, *gh, *wqkvh, *wouth, *wff1h, *wff2h;
    cudaGetSymbolAddress((void**)&t,     g_t);
    cudaGetSymbolAddress((void**)&s1,    g_s1);
    cudaGetSymbolAddress((void**)&ff,    g_ff);
    cudaGetSymbolAddress((void**)&qkvh,  g_qkvh);
    cudaGetSymbolAddress((void**)&ah,    g_ah);
    cudaGetSymbolAddress((void**)&fh,    g_fh);
    cudaGetSymbolAddress((void**)&oh,    g_oh);
    cudaGetSymbolAddress((void**)&gh,    g_gh);
    cudaGetSymbolAddress((void**)&wqkvh, g_wqkvh);
    cudaGetSymbolAddress((void**)&wouth, g_wouth);
    cudaGetSymbolAddress((void**)&wff1h, g_wff1h);
    cudaGetSymbolAddress((void**)&wff2h, g_wff2h);

    cudaFuncSetAttribute(attn_mma_kernel, cudaFuncAttributeMaxDynamicSharedMemorySize, ATT_SMEM_B);
    cudaFuncSetAttribute(ln_tile_kernel,  cudaFuncAttributeMaxDynamicSharedMemorySize, LN_SMEM);
    cudaFuncSetAttribute(hgemm_kernel,    cudaFuncAttributeMaxDynamicSharedMemorySize, HG_SMEM);

    static cudaStream_t s2 = nullptr;
    static cudaEvent_t ev0 = nullptr, evFork = nullptr, evJoin = nullptr;
    if (!s2) {
        cudaStreamCreateWithFlags(&s2, cudaStreamNonBlocking);
        cudaEventCreateWithFlags(&ev0,    cudaEventDisableTiming);
        cudaEventCreateWithFlags(&evFork, cudaEventDisableTiming);
        cudaEventCreateWithFlags(&evJoin, cudaEventDisableTiming);
    }

    // weight converts: FF pair on s2, attention pair on s0 (one launch each)
    cudaEventRecord(ev0, 0);
    cudaStreamWaitEvent(s2, ev0, 0);
    f2h2_kernel<<<(C_*HID + HID*C_)/1024, 256, 0, s2>>>(w_ff1, wff1h, C_*HID, w_ff2, wff2h);
    f2h2_kernel<<<(C_*3*INNER + INNER*C_)/1024, 256>>>(w_qkv, wqkvh, C_*3*INNER, w_out, wouth);

    // transpose + LN1 + LN2 (fp16 a/f)
    ln_tile_kernel<<<dim3(HW_/32, B_), 256, LN_SMEM>>>(x, ln1_g, ln1_b, ln2_g, ln2_b, t, ah, fh);

    cudaEventRecord(evFork, 0);
    cudaStreamWaitEvent(s2, evFork, 0);

    // FF branch (s2)
    hgemm_kernel<<<dim3(HID/128, MTOT/128), 256, HG_SMEM, s2>>>(fh, wff1h, gh,
        MTOT, HID, C_, b_ff1, nullptr, 1, 1);
    hgemm_kernel<<<dim3(C_/128, MTOT/128), 256, HG_SMEM, s2>>>(gh, wff2h, ff,
        MTOT, C_, HID, b_ff2, nullptr, 0, 0);
    cudaEventRecord(evJoin, s2);

    // Attention branch (s0)
    hgemm_kernel<<<dim3(3*INNER/128, MTOT/128), 256, HG_SMEM>>>(ah, wqkvh, qkvh,
        MTOT, 3*INNER, C_, nullptr, nullptr, 0, 1);
    attn_mma_kernel<<<B_*HEADS, 256, ATT_SMEM_B>>>(qkvh, bias_table, oh);
    hgemm_kernel<<<dim3(C_/128, MTOT/128), 256, HG_SMEM>>>(oh, wouth, s1,
        MTOT, C_, INNER, b_out, t, 0, 0);

    // join + fused add-transpose
    cudaStreamWaitEvent(0, evJoin, 0);
    transpose_add_kernel<<<dim3(C_/32, HW_/32, B_), dim3(32, 8)>>>(s1, ff, (float*)d_out);
}